// round 5
// baseline (speedup 1.0000x reference)
#include <cuda_runtime.h>
#include <cuda_bf16.h>
#include <cstdint>

#define DIM    384
#define HEADS  12
#define TOK    49
#define HD     32
#define NTOK   3136
#define BATCH  32
#define M_TOTAL (BATCH * NTOK)   // 100352 rows
#define QKV_N  (3 * DIM)         // 1152
#define NWIN   (M_TOTAL / TOK)   // 2048 windows total

// Scratch (static device globals — allocation-free per harness rules)
__device__ float g_qkv[(size_t)M_TOTAL * QKV_N];   // [100352, 1152]
__device__ float g_att[(size_t)M_TOTAL * DIM];     // [100352, 384]
__device__ float g_bias[HEADS * TOK * TOK];        // [12, 49, 49]

// ---------------------------------------------------------------------------
// Kernel 1: gather relative-position bias into [H, 49, 49]
// ---------------------------------------------------------------------------
__global__ void bias_kernel(const float* __restrict__ table,
                            const int* __restrict__ ridx) {
    int i = blockIdx.x * blockDim.x + threadIdx.x;
    if (i < TOK * TOK * HEADS) {
        int h = i % HEADS;
        int p = i / HEADS;
        g_bias[h * TOK * TOK + p] = table[ridx[p] * HEADS + h];
    }
}

// ---------------------------------------------------------------------------
__device__ __forceinline__ unsigned int f2tf(float f) {
    unsigned int r;
    asm("cvt.rna.tf32.f32 %0, %1;" : "=r"(r) : "f"(f));
    return r;
}

// ---------------------------------------------------------------------------
// Kernel 2/4: tf32 tensor-core GEMM, 2-stage smem double buffer with
// FRAGMENT-PACKED smem layout: each thread's mma operands are contiguous
// uint4 (A) / uint2 (B), so fragment loads are 8 vector LDS per k8-step
// instead of 24 scalar LDS.
// C = A[M,K] @ B[K,N] + bias[N]. 128x128 CTA, BK=16, 256 thr, warp 64x32.
//
// Fragment layout for mma.m16n8k8 (lane = g*4+t, g=lane>>2, t=lane&3):
//   A regs: a0=(k=t,   m=g), a1=(k=t,   m=g+8), a2=(k=t+4, m=g), a3=(k=t+4, m=g+8)
//   B regs: b0=(k=t, n=g), b1=(k=t+4, n=g)
// Packed: Apk[ks][mblk][lane][reg], reg = ((m>>3)&1) + 2*((k&7)>>2)
//         Bpk[ks][nblk][lane][reg], reg = (k&7)>>2
// ---------------------------------------------------------------------------
__global__ __launch_bounds__(256)
void gemm_tf32(const float* __restrict__ A, const float* __restrict__ B,
               const float* __restrict__ bias, float* __restrict__ C,
               int M, int N, int K) {
    const int BM = 128, BN = 128, BK = 16;
    __shared__ unsigned int Apk[2][2][8][32][4];   // buf, ks, mblk, lane, reg
    __shared__ unsigned int Bpk[2][2][16][32][2];  // buf, ks, nblk, lane, reg

    int tid  = threadIdx.x;
    int lane = tid & 31;
    int warp = tid >> 5;
    int wmb = (warp >> 2) * 4;   // warp m-block base (0 or 4), blocks of 16
    int wnb = (warp & 3) * 4;    // warp n-block base (0,4,8,12), blocks of 8
    int g = lane >> 2;
    int t = lane & 3;

    int bm = blockIdx.y * BM;
    int bn = blockIdx.x * BN;

    float acc[4][4][4];
    #pragma unroll
    for (int i = 0; i < 4; i++)
        #pragma unroll
        for (int j = 0; j < 4; j++)
            #pragma unroll
            for (int r = 0; r < 4; r++) acc[i][j][r] = 0.f;

    // global load mapping
    int arow = tid >> 2;        // 0..63 (A rows; +64 second half)
    int aq   = (tid & 3) * 4;   // A k within BK: 0,4,8,12
    int brow = tid >> 4;        // 0..15 (B k)
    int bq   = (tid & 15) * 4;  // B n: 0..60 (first half), +64 second

    // writer-side precomputed indices
    int a_ks    = aq >> 3;            // 0 or 1
    int a_khalf = (aq & 7) >> 2;      // 0 or 1
    int a_mb0   = arow >> 4;          // 0..3
    int a_g     = arow & 7;
    int a_half  = (arow >> 3) & 1;
    int a_reg   = a_half + 2 * a_khalf;

    int b_ks   = brow >> 3;
    int b_kk   = brow & 7;
    int b_t    = b_kk & 3;
    int b_reg  = b_kk >> 2;
    int b_nb0  = bq >> 3;             // 0..7
    int b_g0   = bq & 7;              // 0 or 4

    const float* Ap0 = A + (size_t)(bm + arow) * K + aq;
    const float* Ap1 = A + (size_t)(bm + arow + 64) * K + aq;

    float4 a0v, a1v, b0v, b1v;

    a0v = *(const float4*)(Ap0);
    a1v = *(const float4*)(Ap1);
    {
        const float* bp = B + (size_t)brow * N + bn;
        b0v = *(const float4*)(bp + bq);
        b1v = *(const float4*)(bp + bq + 64);
    }

    #define STORE_STAGE(buf)                                                  \
        do {                                                                  \
            unsigned int* pa0 = &Apk[buf][a_ks][a_mb0][a_g * 4][a_reg];       \
            unsigned int* pa1 = &Apk[buf][a_ks][a_mb0 + 4][a_g * 4][a_reg];   \
            pa0[0]  = f2tf(a0v.x);  pa0[4]  = f2tf(a0v.y);                    \
            pa0[8]  = f2tf(a0v.z);  pa0[12] = f2tf(a0v.w);                    \
            pa1[0]  = f2tf(a1v.x);  pa1[4]  = f2tf(a1v.y);                    \
            pa1[8]  = f2tf(a1v.z);  pa1[12] = f2tf(a1v.w);                    \
            unsigned int* pb0 = &Bpk[buf][b_ks][b_nb0][b_g0 * 4 + b_t][b_reg];\
            unsigned int* pb1 = &Bpk[buf][b_ks][b_nb0 + 8][b_g0 * 4 + b_t][b_reg];\
            pb0[0]  = f2tf(b0v.x);  pb0[8]  = f2tf(b0v.y);                    \
            pb0[16] = f2tf(b0v.z);  pb0[24] = f2tf(b0v.w);                    \
            pb1[0]  = f2tf(b1v.x);  pb1[8]  = f2tf(b1v.y);                    \
            pb1[16] = f2tf(b1v.z);  pb1[24] = f2tf(b1v.w);                    \
        } while (0)

    #define COMPUTE_STAGE(buf)                                                \
        do {                                                                  \
            _Pragma("unroll")                                                 \
            for (int ks = 0; ks < 2; ks++) {                                  \
                uint4 af[4];                                                  \
                uint2 bf[4];                                                  \
                _Pragma("unroll")                                             \
                for (int mt = 0; mt < 4; mt++)                                \
                    af[mt] = *(const uint4*)&Apk[buf][ks][wmb + mt][lane][0]; \
                _Pragma("unroll")                                             \
                for (int nt = 0; nt < 4; nt++)                                \
                    bf[nt] = *(const uint2*)&Bpk[buf][ks][wnb + nt][lane][0]; \
                _Pragma("unroll")                                             \
                for (int mt = 0; mt < 4; mt++)                                \
                    _Pragma("unroll")                                         \
                    for (int nt = 0; nt < 4; nt++) {                          \
                        asm volatile(                                         \
                            "mma.sync.aligned.m16n8k8.row.col.f32.tf32.tf32.f32 " \
                            "{%0,%1,%2,%3}, {%4,%5,%6,%7}, {%8,%9}, {%0,%1,%2,%3};" \
                            : "+f"(acc[mt][nt][0]), "+f"(acc[mt][nt][1]),     \
                              "+f"(acc[mt][nt][2]), "+f"(acc[mt][nt][3])      \
                            : "r"(af[mt].x), "r"(af[mt].y),                   \
                              "r"(af[mt].z), "r"(af[mt].w),                   \
                              "r"(bf[nt].x), "r"(bf[nt].y));                  \
                    }                                                         \
            }                                                                 \
        } while (0)

    STORE_STAGE(0);
    __syncthreads();

    int cur = 0;
    for (int k0 = BK; k0 < K; k0 += BK) {
        a0v = *(const float4*)(Ap0 + k0);
        a1v = *(const float4*)(Ap1 + k0);
        const float* bp = B + (size_t)(k0 + brow) * N + bn;
        b0v = *(const float4*)(bp + bq);
        b1v = *(const float4*)(bp + bq + 64);
        COMPUTE_STAGE(cur);
        STORE_STAGE(cur ^ 1);
        __syncthreads();
        cur ^= 1;
    }
    COMPUTE_STAGE(cur);

    // epilogue: c0:(g,2t) c1:(g,2t+1) c2:(g+8,2t) c3:(g+8,2t+1)
    #pragma unroll
    for (int mt = 0; mt < 4; mt++) {
        int row0 = bm + wmb * 16 + mt * 16 + g;
        #pragma unroll
        for (int nt = 0; nt < 4; nt++) {
            int col = bn + wnb * 8 + nt * 8 + 2 * t;
            float bx = bias[col], by = bias[col + 1];
            float2 o0 = make_float2(acc[mt][nt][0] + bx, acc[mt][nt][1] + by);
            float2 o1 = make_float2(acc[mt][nt][2] + bx, acc[mt][nt][3] + by);
            *(float2*)&C[(size_t)row0 * N + col]       = o0;
            *(float2*)&C[(size_t)(row0 + 8) * N + col] = o1;
        }
    }
    #undef STORE_STAGE
    #undef COMPUTE_STAGE
}

// ---------------------------------------------------------------------------
// Kernel 3: windowed attention, register-tiled (unchanged from R4).
// ---------------------------------------------------------------------------
#define TOKP 52
__global__ __launch_bounds__(256)
void attn_kernel(float* __restrict__ out) {
    int w = blockIdx.x;
    int h = blockIdx.y;
    __shared__ float qT[HD][TOKP];
    __shared__ float kT[HD][TOKP];
    __shared__ float v[TOK][HD];
    __shared__ float s[TOKP][TOKP];

    int tid = threadIdx.x;
    const float scale = 0.17677669529663687f;  // 32^-0.5

    for (int i = tid; i < HD * 3; i += 256) {
        int dd = i / 3, tp = TOK + i % 3;
        qT[dd][tp] = 0.f;
        kT[dd][tp] = 0.f;
    }

    size_t base = (size_t)w * TOK * QKV_N + (size_t)h * HD;
    for (int i = tid; i < TOK * (HD / 4); i += 256) {
        int t = i / (HD / 4), dq = (i % (HD / 4)) * 4;
        const float* row = g_qkv + base + (size_t)t * QKV_N + dq;
        float4 qv = *(const float4*)(row);
        float4 kv = *(const float4*)(row + DIM);
        float4 vv = *(const float4*)(row + 2 * DIM);
        qT[dq + 0][t] = qv.x * scale;
        qT[dq + 1][t] = qv.y * scale;
        qT[dq + 2][t] = qv.z * scale;
        qT[dq + 3][t] = qv.w * scale;
        kT[dq + 0][t] = kv.x;
        kT[dq + 1][t] = kv.y;
        kT[dq + 2][t] = kv.z;
        kT[dq + 3][t] = kv.w;
        *(float4*)&v[t][dq] = vv;
    }
    __syncthreads();

    const float* bptr = g_bias + h * TOK * TOK;
    if (tid < 169) {
        int i0 = (tid / 13) * 4;
        int j0 = (tid % 13) * 4;
        float acc[4][4];
        #pragma unroll
        for (int r = 0; r < 4; r++)
            #pragma unroll
            for (int c = 0; c < 4; c++) acc[r][c] = 0.f;
        #pragma unroll
        for (int dd = 0; dd < HD; dd++) {
            float4 qa = *(const float4*)&qT[dd][i0];
            float4 ka = *(const float4*)&kT[dd][j0];
            float qr[4] = {qa.x, qa.y, qa.z, qa.w};
            float kc[4] = {ka.x, ka.y, ka.z, ka.w};
            #pragma unroll
            for (int r = 0; r < 4; r++)
                #pragma unroll
                for (int c = 0; c < 4; c++)
                    acc[r][c] = fmaf(qr[r], kc[c], acc[r][c]);
        }
        #pragma unroll
        for (int r = 0; r < 4; r++) {
            int i = i0 + r;
            #pragma unroll
            for (int c = 0; c < 4; c++) {
                int j = j0 + c;
                float b = (i < TOK && j < TOK) ? bptr[i * TOK + j] : 0.f;
                s[i][j] = acc[r][c] + b;
            }
        }
    }
    __syncthreads();

    if (tid < TOK) {
        float mx = -1e30f;
        #pragma unroll 7
        for (int j = 0; j < TOK; j++) mx = fmaxf(mx, s[tid][j]);
        float sum = 0.f;
        #pragma unroll 7
        for (int j = 0; j < TOK; j++) {
            float e = __expf(s[tid][j] - mx);
            s[tid][j] = e;
            sum += e;
        }
        float inv = 1.0f / sum;
        #pragma unroll 7
        for (int j = 0; j < TOK; j++) s[tid][j] *= inv;
    }
    __syncthreads();

    for (int p = tid; p < TOK * (HD / 4); p += 256) {
        int i = p / (HD / 4), dq = (p % (HD / 4)) * 4;
        float ox = 0.f, oy = 0.f, oz = 0.f, ow = 0.f;
        #pragma unroll 7
        for (int j = 0; j < TOK; j++) {
            float sv = s[i][j];
            float4 vv = *(const float4*)&v[j][dq];
            ox = fmaf(sv, vv.x, ox);
            oy = fmaf(sv, vv.y, oy);
            oz = fmaf(sv, vv.z, oz);
            ow = fmaf(sv, vv.w, ow);
        }
        float4 o = make_float4(ox, oy, oz, ow);
        *(float4*)&out[((size_t)w * TOK + i) * DIM + h * HD + dq] = o;
    }
}

// ---------------------------------------------------------------------------
extern "C" void kernel_launch(void* const* d_in, const int* in_sizes, int n_in,
                              void* d_out, int out_size) {
    const float* x       = (const float*)d_in[0];
    const float* qkv_w   = (const float*)d_in[1];
    const float* qkv_b   = (const float*)d_in[2];
    const float* proj_w  = (const float*)d_in[3];
    const float* proj_b  = (const float*)d_in[4];
    const float* table   = (const float*)d_in[5];
    const int*   ridx    = (const int*)d_in[6];
    float*       out     = (float*)d_out;

    float *qkv_buf = nullptr, *att_buf = nullptr;
    cudaGetSymbolAddress((void**)&qkv_buf, g_qkv);
    cudaGetSymbolAddress((void**)&att_buf, g_att);

    {
        int total = TOK * TOK * HEADS;
        bias_kernel<<<(total + 255) / 256, 256>>>(table, ridx);
    }
    {
        dim3 grid(QKV_N / 128, M_TOTAL / 128);   // (9, 784)
        gemm_tf32<<<grid, 256>>>(x, qkv_w, qkv_b, qkv_buf, M_TOTAL, QKV_N, DIM);
    }
    {
        dim3 grid(NWIN, HEADS);                  // (2048, 12)
        attn_kernel<<<grid, 256>>>(att_buf);
    }
    {
        dim3 grid(DIM / 128, M_TOTAL / 128);     // (3, 784)
        gemm_tf32<<<grid, 256>>>(att_buf, proj_w, proj_b, out, M_TOTAL, DIM, DIM);
    }
}

// round 6
// speedup vs baseline: 1.4389x; 1.4389x over previous
#include <cuda_runtime.h>
#include <cuda_bf16.h>
#include <cstdint>

#define DIM    384
#define HEADS  12
#define TOK    49
#define HD     32
#define NTOK   3136
#define BATCH  32
#define M_TOTAL (BATCH * NTOK)   // 100352 rows
#define QKV_N  (3 * DIM)         // 1152
#define NWIN   (M_TOTAL / TOK)   // 2048 windows total

// Scratch (static device globals — allocation-free per harness rules)
__device__ float g_x  [(size_t)M_TOTAL * DIM];     // tf32-rounded x
__device__ float g_w1 [DIM * QKV_N];               // tf32-rounded qkv_w
__device__ float g_w2 [DIM * DIM];                 // tf32-rounded proj_w
__device__ float g_qkv[(size_t)M_TOTAL * QKV_N];   // [100352, 1152]
__device__ float g_att[(size_t)M_TOTAL * DIM];     // [100352, 384] (tf32-rounded)
__device__ float g_bias[HEADS * TOK * TOK];        // [12, 49, 49]

// ---------------------------------------------------------------------------
__device__ __forceinline__ unsigned int f2tf(float f) {
    unsigned int r;
    asm("cvt.rna.tf32.f32 %0, %1;" : "=r"(r) : "f"(f));
    return r;
}
__device__ __forceinline__ unsigned int fu(float f) { return __float_as_uint(f); }

// ---------------------------------------------------------------------------
// Kernel 0: elementwise tf32 rounding (rna), float4 vectorized.
// ---------------------------------------------------------------------------
__global__ void round_tf32(const float* __restrict__ in, float* __restrict__ out,
                           int n4) {
    int i = blockIdx.x * blockDim.x + threadIdx.x;
    if (i < n4) {
        float4 v = ((const float4*)in)[i];
        v.x = __uint_as_float(f2tf(v.x));
        v.y = __uint_as_float(f2tf(v.y));
        v.z = __uint_as_float(f2tf(v.z));
        v.w = __uint_as_float(f2tf(v.w));
        ((float4*)out)[i] = v;
    }
}

// ---------------------------------------------------------------------------
// Kernel 1: gather relative-position bias into [H, 49, 49]
// ---------------------------------------------------------------------------
__global__ void bias_kernel(const float* __restrict__ table,
                            const int* __restrict__ ridx) {
    int i = blockIdx.x * blockDim.x + threadIdx.x;
    if (i < TOK * TOK * HEADS) {
        int h = i % HEADS;
        int p = i / HEADS;
        g_bias[h * TOK * TOK + p] = table[ridx[p] * HEADS + h];
    }
}

// ---------------------------------------------------------------------------
// Kernel 2/4: tf32 tensor-core GEMM with 3-stage cp.async pipeline.
// Inputs must be pre-rounded to tf32-representable fp32.
// C = A[M,K] @ B[K,N] + bias[N]. 128x128 CTA, BK=16, 256 thr, warp 64x32.
// A smem: [m(128)][k(16)+4pad]  (row 80B, 16B-aligned; frag reads conflict-free)
// B smem: [k(16)][n(128)+8pad]
// ---------------------------------------------------------------------------
#define STAGES 3
struct SmemGemm {
    float A[STAGES][128][20];
    float B[STAGES][16][136];
};
#define GEMM_SMEM_BYTES (sizeof(SmemGemm))

__device__ __forceinline__ void cpa16(void* dst, const void* src) {
    unsigned int s = (unsigned int)__cvta_generic_to_shared(dst);
    asm volatile("cp.async.cg.shared.global [%0], [%1], 16;" :: "r"(s), "l"(src));
}

__global__ __launch_bounds__(256)
void gemm_tf32(const float* __restrict__ A, const float* __restrict__ B,
               const float* __restrict__ bias, float* __restrict__ C,
               int M, int N, int K) {
    extern __shared__ char dynsmem[];
    SmemGemm* sm = (SmemGemm*)dynsmem;

    const int BK = 16;
    int tid  = threadIdx.x;
    int lane = tid & 31;
    int warp = tid >> 5;
    int wm = (warp >> 2) * 64;
    int wn = (warp & 3) * 32;
    int g = lane >> 2;
    int t = lane & 3;

    int bm = blockIdx.y * 128;
    int bn = blockIdx.x * 128;

    float acc[4][4][4];
    #pragma unroll
    for (int i = 0; i < 4; i++)
        #pragma unroll
        for (int j = 0; j < 4; j++)
            #pragma unroll
            for (int r = 0; r < 4; r++) acc[i][j][r] = 0.f;

    // cp.async chunk mapping: 2 A-chunks + 2 B-chunks of 16B per thread.
    // A: chunk c in [0,512): row=c>>2, kq=(c&3)*4
    // B: chunk c in [0,512): row=c>>5, nq=(c&31)*4
    int ac0 = tid * 2;
    int a_r0 = ac0 >> 2,        a_k0 = (ac0 & 3) * 4;
    int a_r1 = (ac0 + 1) >> 2,  a_k1 = ((ac0 + 1) & 3) * 4;
    int b_r0 = ac0 >> 5,        b_n0 = (ac0 & 31) * 4;
    int b_r1 = (ac0 + 1) >> 5,  b_n1 = ((ac0 + 1) & 31) * 4;

    #define ISSUE_TILE(buf, k0)                                               \
        do {                                                                  \
            cpa16(&sm->A[buf][a_r0][a_k0], A + (size_t)(bm + a_r0) * K + (k0) + a_k0); \
            cpa16(&sm->A[buf][a_r1][a_k1], A + (size_t)(bm + a_r1) * K + (k0) + a_k1); \
            cpa16(&sm->B[buf][b_r0][b_n0], B + (size_t)((k0) + b_r0) * N + bn + b_n0); \
            cpa16(&sm->B[buf][b_r1][b_n1], B + (size_t)((k0) + b_r1) * N + bn + b_n1); \
            asm volatile("cp.async.commit_group;");                           \
        } while (0)

    #define COMPUTE_STAGE(buf)                                                \
        do {                                                                  \
            _Pragma("unroll")                                                 \
            for (int ks = 0; ks < 2; ks++) {                                  \
                int kb = ks * 8;                                              \
                uint4 af[4];                                                  \
                uint2 bf[4];                                                  \
                _Pragma("unroll")                                             \
                for (int mt = 0; mt < 4; mt++) {                              \
                    int m0 = wm + mt * 16;                                    \
                    af[mt].x = fu(sm->A[buf][m0 + g][kb + t]);                \
                    af[mt].y = fu(sm->A[buf][m0 + g + 8][kb + t]);            \
                    af[mt].z = fu(sm->A[buf][m0 + g][kb + t + 4]);            \
                    af[mt].w = fu(sm->A[buf][m0 + g + 8][kb + t + 4]);        \
                }                                                             \
                _Pragma("unroll")                                             \
                for (int nt = 0; nt < 4; nt++) {                              \
                    int n0 = wn + nt * 8;                                     \
                    bf[nt].x = fu(sm->B[buf][kb + t][n0 + g]);                \
                    bf[nt].y = fu(sm->B[buf][kb + t + 4][n0 + g]);            \
                }                                                             \
                _Pragma("unroll")                                             \
                for (int mt = 0; mt < 4; mt++)                                \
                    _Pragma("unroll")                                         \
                    for (int nt = 0; nt < 4; nt++) {                          \
                        asm volatile(                                         \
                            "mma.sync.aligned.m16n8k8.row.col.f32.tf32.tf32.f32 " \
                            "{%0,%1,%2,%3}, {%4,%5,%6,%7}, {%8,%9}, {%0,%1,%2,%3};" \
                            : "+f"(acc[mt][nt][0]), "+f"(acc[mt][nt][1]),     \
                              "+f"(acc[mt][nt][2]), "+f"(acc[mt][nt][3])      \
                            : "r"(af[mt].x), "r"(af[mt].y),                   \
                              "r"(af[mt].z), "r"(af[mt].w),                   \
                              "r"(bf[nt].x), "r"(bf[nt].y));                  \
                    }                                                         \
            }                                                                 \
        } while (0)

    int T = K / BK;  // 24

    ISSUE_TILE(0, 0);
    ISSUE_TILE(1, BK);

    for (int i = 0; i < T; i++) {
        if (i + 1 < T) {
            asm volatile("cp.async.wait_group 1;");
        } else {
            asm volatile("cp.async.wait_group 0;");
        }
        __syncthreads();
        if (i + 2 < T) {
            int b = (i + 2) % STAGES;
            int k0 = (i + 2) * BK;
            ISSUE_TILE(b, k0);
        }
        COMPUTE_STAGE(i % STAGES);
        // next iteration's syncthreads (after wait) protects buffer reuse
        if (i + 1 < T) __syncthreads();
    }

    // epilogue: c0:(g,2t) c1:(g,2t+1) c2:(g+8,2t) c3:(g+8,2t+1)
    #pragma unroll
    for (int mt = 0; mt < 4; mt++) {
        int row0 = bm + wm + mt * 16 + g;
        #pragma unroll
        for (int nt = 0; nt < 4; nt++) {
            int col = bn + wn + nt * 8 + 2 * t;
            float bx = bias[col], by = bias[col + 1];
            float2 o0 = make_float2(acc[mt][nt][0] + bx, acc[mt][nt][1] + by);
            float2 o1 = make_float2(acc[mt][nt][2] + bx, acc[mt][nt][3] + by);
            *(float2*)&C[(size_t)row0 * N + col]       = o0;
            *(float2*)&C[(size_t)(row0 + 8) * N + col] = o1;
        }
    }
    #undef ISSUE_TILE
    #undef COMPUTE_STAGE
}

// ---------------------------------------------------------------------------
// Kernel 3: windowed attention, register-tiled (R4 layout).
// Output rounded to tf32 (rna) so proj GEMM can consume it raw.
// ---------------------------------------------------------------------------
#define TOKP 52
__global__ __launch_bounds__(256)
void attn_kernel(float* __restrict__ out) {
    int w = blockIdx.x;
    int h = blockIdx.y;
    __shared__ float qT[HD][TOKP];
    __shared__ float kT[HD][TOKP];
    __shared__ float v[TOK][HD];
    __shared__ float s[TOKP][TOKP];

    int tid = threadIdx.x;
    const float scale = 0.17677669529663687f;  // 32^-0.5

    for (int i = tid; i < HD * 3; i += 256) {
        int dd = i / 3, tp = TOK + i % 3;
        qT[dd][tp] = 0.f;
        kT[dd][tp] = 0.f;
    }

    size_t base = (size_t)w * TOK * QKV_N + (size_t)h * HD;
    for (int i = tid; i < TOK * (HD / 4); i += 256) {
        int t = i / (HD / 4), dq = (i % (HD / 4)) * 4;
        const float* row = g_qkv + base + (size_t)t * QKV_N + dq;
        float4 qv = *(const float4*)(row);
        float4 kv = *(const float4*)(row + DIM);
        float4 vv = *(const float4*)(row + 2 * DIM);
        qT[dq + 0][t] = qv.x * scale;
        qT[dq + 1][t] = qv.y * scale;
        qT[dq + 2][t] = qv.z * scale;
        qT[dq + 3][t] = qv.w * scale;
        kT[dq + 0][t] = kv.x;
        kT[dq + 1][t] = kv.y;
        kT[dq + 2][t] = kv.z;
        kT[dq + 3][t] = kv.w;
        *(float4*)&v[t][dq] = vv;
    }
    __syncthreads();

    const float* bptr = g_bias + h * TOK * TOK;
    if (tid < 169) {
        int i0 = (tid / 13) * 4;
        int j0 = (tid % 13) * 4;
        float acc[4][4];
        #pragma unroll
        for (int r = 0; r < 4; r++)
            #pragma unroll
            for (int c = 0; c < 4; c++) acc[r][c] = 0.f;
        #pragma unroll
        for (int dd = 0; dd < HD; dd++) {
            float4 qa = *(const float4*)&qT[dd][i0];
            float4 ka = *(const float4*)&kT[dd][j0];
            float qr[4] = {qa.x, qa.y, qa.z, qa.w};
            float kc[4] = {ka.x, ka.y, ka.z, ka.w};
            #pragma unroll
            for (int r = 0; r < 4; r++)
                #pragma unroll
                for (int c = 0; c < 4; c++)
                    acc[r][c] = fmaf(qr[r], kc[c], acc[r][c]);
        }
        #pragma unroll
        for (int r = 0; r < 4; r++) {
            int i = i0 + r;
            #pragma unroll
            for (int c = 0; c < 4; c++) {
                int j = j0 + c;
                float b = (i < TOK && j < TOK) ? bptr[i * TOK + j] : 0.f;
                s[i][j] = acc[r][c] + b;
            }
        }
    }
    __syncthreads();

    if (tid < TOK) {
        float mx = -1e30f;
        #pragma unroll 7
        for (int j = 0; j < TOK; j++) mx = fmaxf(mx, s[tid][j]);
        float sum = 0.f;
        #pragma unroll 7
        for (int j = 0; j < TOK; j++) {
            float e = __expf(s[tid][j] - mx);
            s[tid][j] = e;
            sum += e;
        }
        float inv = 1.0f / sum;
        #pragma unroll 7
        for (int j = 0; j < TOK; j++) s[tid][j] *= inv;
    }
    __syncthreads();

    for (int p = tid; p < TOK * (HD / 4); p += 256) {
        int i = p / (HD / 4), dq = (p % (HD / 4)) * 4;
        float ox = 0.f, oy = 0.f, oz = 0.f, ow = 0.f;
        #pragma unroll 7
        for (int j = 0; j < TOK; j++) {
            float sv = s[i][j];
            float4 vv = *(const float4*)&v[j][dq];
            ox = fmaf(sv, vv.x, ox);
            oy = fmaf(sv, vv.y, oy);
            oz = fmaf(sv, vv.z, oz);
            ow = fmaf(sv, vv.w, ow);
        }
        // round to tf32 so proj GEMM reads it raw (numerics == rna cvt path)
        float4 o;
        o.x = __uint_as_float(f2tf(ox));
        o.y = __uint_as_float(f2tf(oy));
        o.z = __uint_as_float(f2tf(oz));
        o.w = __uint_as_float(f2tf(ow));
        *(float4*)&out[((size_t)w * TOK + i) * DIM + h * HD + dq] = o;
    }
}

// ---------------------------------------------------------------------------
extern "C" void kernel_launch(void* const* d_in, const int* in_sizes, int n_in,
                              void* d_out, int out_size) {
    const float* x       = (const float*)d_in[0];
    const float* qkv_w   = (const float*)d_in[1];
    const float* qkv_b   = (const float*)d_in[2];
    const float* proj_w  = (const float*)d_in[3];
    const float* proj_b  = (const float*)d_in[4];
    const float* table   = (const float*)d_in[5];
    const int*   ridx    = (const int*)d_in[6];
    float*       out     = (float*)d_out;

    float *xr = nullptr, *w1 = nullptr, *w2 = nullptr;
    float *qkv_buf = nullptr, *att_buf = nullptr;
    cudaGetSymbolAddress((void**)&xr, g_x);
    cudaGetSymbolAddress((void**)&w1, g_w1);
    cudaGetSymbolAddress((void**)&w2, g_w2);
    cudaGetSymbolAddress((void**)&qkv_buf, g_qkv);
    cudaGetSymbolAddress((void**)&att_buf, g_att);

    static bool attr_set = false;
    if (!attr_set) {
        cudaFuncSetAttribute(gemm_tf32,
                             cudaFuncAttributeMaxDynamicSharedMemorySize,
                             (int)GEMM_SMEM_BYTES);
        attr_set = true;
    }

    // 0. pre-round inputs/weights to tf32
    {
        int n4 = (M_TOTAL * DIM) / 4;
        round_tf32<<<(n4 + 255) / 256, 256>>>(x, xr, n4);
        int w14 = (DIM * QKV_N) / 4;
        round_tf32<<<(w14 + 255) / 256, 256>>>(qkv_w, w1, w14);
        int w24 = (DIM * DIM) / 4;
        round_tf32<<<(w24 + 255) / 256, 256>>>(proj_w, w2, w24);
    }
    // 1. bias gather
    {
        int total = TOK * TOK * HEADS;
        bias_kernel<<<(total + 255) / 256, 256>>>(table, ridx);
    }
    // 2. QKV GEMM: [100352,384] @ [384,1152] + qkv_b
    {
        dim3 grid(QKV_N / 128, M_TOTAL / 128);   // (9, 784)
        gemm_tf32<<<grid, 256, GEMM_SMEM_BYTES>>>(xr, w1, qkv_b, qkv_buf,
                                                  M_TOTAL, QKV_N, DIM);
    }
    // 3. window attention
    {
        dim3 grid(NWIN, HEADS);                  // (2048, 12)
        attn_kernel<<<grid, 256>>>(att_buf);
    }
    // 4. proj GEMM: [100352,384] @ [384,384] + proj_b -> d_out
    {
        dim3 grid(DIM / 128, M_TOTAL / 128);     // (3, 784)
        gemm_tf32<<<grid, 256, GEMM_SMEM_BYTES>>>(att_buf, w2, proj_b, out,
                                                  M_TOTAL, DIM, DIM);
    }
}

// round 7
// speedup vs baseline: 1.8891x; 1.3129x over previous
#include <cuda_runtime.h>
#include <cuda_bf16.h>
#include <cstdint>

#define DIM    384
#define HEADS  12
#define TOK    49
#define HD     32
#define NTOK   3136
#define BATCH  32
#define M_TOTAL (BATCH * NTOK)   // 100352 rows
#define QKV_N  (3 * DIM)         // 1152
#define NWIN   (M_TOTAL / TOK)   // 2048 windows total

// Scratch (static device globals — allocation-free per harness rules)
__device__ float g_qkv[(size_t)M_TOTAL * QKV_N];   // [100352, 1152]
__device__ float g_att[(size_t)M_TOTAL * DIM];     // [100352, 384]
__device__ float g_bias[HEADS * TOK * TOK];        // [12, 49, 49]

// ---------------------------------------------------------------------------
// Kernel 1: gather relative-position bias into [H, 49, 49]
// ---------------------------------------------------------------------------
__global__ void bias_kernel(const float* __restrict__ table,
                            const int* __restrict__ ridx) {
    int i = blockIdx.x * blockDim.x + threadIdx.x;
    if (i < TOK * TOK * HEADS) {
        int h = i % HEADS;
        int p = i / HEADS;
        g_bias[h * TOK * TOK + p] = table[ridx[p] * HEADS + h];
    }
}

// ---------------------------------------------------------------------------
__device__ __forceinline__ unsigned int f2tf(float f) {
    unsigned int r;
    asm("cvt.rna.tf32.f32 %0, %1;" : "=r"(r) : "f"(f));
    return r;
}

// ---------------------------------------------------------------------------
// Kernel 2/4: tf32 tensor-core GEMM, 2-stage smem double buffer (R4 proven).
// C = A[M,K] @ B[K,N] + bias[N]. 128x128 CTA, BK=16, 256 thr, warp 64x32.
// ---------------------------------------------------------------------------
__global__ __launch_bounds__(256)
void gemm_tf32(const float* __restrict__ A, const float* __restrict__ B,
               const float* __restrict__ bias, float* __restrict__ C,
               int M, int N, int K) {
    const int BM = 128, BN = 128, BK = 16;
    __shared__ unsigned int As[2][BK][BM + 8];
    __shared__ unsigned int Bs[2][BK][BN + 8];

    int tid  = threadIdx.x;
    int lane = tid & 31;
    int warp = tid >> 5;
    int wm = (warp >> 2) * 64;
    int wn = (warp & 3) * 32;
    int g = lane >> 2;
    int t = lane & 3;

    int bm = blockIdx.y * BM;
    int bn = blockIdx.x * BN;

    float acc[4][4][4];
    #pragma unroll
    for (int i = 0; i < 4; i++)
        #pragma unroll
        for (int j = 0; j < 4; j++)
            #pragma unroll
            for (int r = 0; r < 4; r++) acc[i][j][r] = 0.f;

    int arow = tid >> 2;
    int aq   = (tid & 3) * 4;
    int brow = tid >> 4;
    int bq   = (tid & 15) * 4;

    const float* Ap0 = A + (size_t)(bm + arow) * K + aq;
    const float* Ap1 = A + (size_t)(bm + arow + 64) * K + aq;

    float4 a0v, a1v, b0v, b1v;

    a0v = *(const float4*)(Ap0);
    a1v = *(const float4*)(Ap1);
    {
        const float* bp = B + (size_t)brow * N + bn;
        b0v = *(const float4*)(bp + bq);
        b1v = *(const float4*)(bp + bq + 64);
    }
    #define STORE_STAGE(buf)                                                  \
        do {                                                                  \
            As[buf][aq + 0][arow]      = f2tf(a0v.x);                         \
            As[buf][aq + 1][arow]      = f2tf(a0v.y);                         \
            As[buf][aq + 2][arow]      = f2tf(a0v.z);                         \
            As[buf][aq + 3][arow]      = f2tf(a0v.w);                         \
            As[buf][aq + 0][arow + 64] = f2tf(a1v.x);                         \
            As[buf][aq + 1][arow + 64] = f2tf(a1v.y);                         \
            As[buf][aq + 2][arow + 64] = f2tf(a1v.z);                         \
            As[buf][aq + 3][arow + 64] = f2tf(a1v.w);                         \
            uint4 u0 = make_uint4(f2tf(b0v.x), f2tf(b0v.y), f2tf(b0v.z), f2tf(b0v.w)); \
            uint4 u1 = make_uint4(f2tf(b1v.x), f2tf(b1v.y), f2tf(b1v.z), f2tf(b1v.w)); \
            *(uint4*)&Bs[buf][brow][bq]      = u0;                            \
            *(uint4*)&Bs[buf][brow][bq + 64] = u1;                            \
        } while (0)

    #define COMPUTE_STAGE(buf)                                                \
        do {                                                                  \
            _Pragma("unroll")                                                 \
            for (int ks = 0; ks < 2; ks++) {                                  \
                int kb = ks * 8;                                              \
                unsigned int af[4][4];                                        \
                unsigned int bf[4][2];                                        \
                _Pragma("unroll")                                             \
                for (int mt = 0; mt < 4; mt++) {                              \
                    int m0 = wm + mt * 16;                                    \
                    af[mt][0] = As[buf][kb + t][m0 + g];                      \
                    af[mt][1] = As[buf][kb + t][m0 + g + 8];                  \
                    af[mt][2] = As[buf][kb + t + 4][m0 + g];                  \
                    af[mt][3] = As[buf][kb + t + 4][m0 + g + 8];              \
                }                                                             \
                _Pragma("unroll")                                             \
                for (int nt = 0; nt < 4; nt++) {                              \
                    int n0 = wn + nt * 8;                                     \
                    bf[nt][0] = Bs[buf][kb + t][n0 + g];                      \
                    bf[nt][1] = Bs[buf][kb + t + 4][n0 + g];                  \
                }                                                             \
                _Pragma("unroll")                                             \
                for (int mt = 0; mt < 4; mt++)                                \
                    _Pragma("unroll")                                         \
                    for (int nt = 0; nt < 4; nt++) {                          \
                        asm volatile(                                         \
                            "mma.sync.aligned.m16n8k8.row.col.f32.tf32.tf32.f32 " \
                            "{%0,%1,%2,%3}, {%4,%5,%6,%7}, {%8,%9}, {%0,%1,%2,%3};" \
                            : "+f"(acc[mt][nt][0]), "+f"(acc[mt][nt][1]),     \
                              "+f"(acc[mt][nt][2]), "+f"(acc[mt][nt][3])      \
                            : "r"(af[mt][0]), "r"(af[mt][1]),                 \
                              "r"(af[mt][2]), "r"(af[mt][3]),                 \
                              "r"(bf[nt][0]), "r"(bf[nt][1]));                \
                    }                                                         \
            }                                                                 \
        } while (0)

    STORE_STAGE(0);
    __syncthreads();

    int cur = 0;
    for (int k0 = BK; k0 < K; k0 += BK) {
        a0v = *(const float4*)(Ap0 + k0);
        a1v = *(const float4*)(Ap1 + k0);
        const float* bp = B + (size_t)(k0 + brow) * N + bn;
        b0v = *(const float4*)(bp + bq);
        b1v = *(const float4*)(bp + bq + 64);
        COMPUTE_STAGE(cur);
        STORE_STAGE(cur ^ 1);
        __syncthreads();
        cur ^= 1;
    }
    COMPUTE_STAGE(cur);

    #pragma unroll
    for (int mt = 0; mt < 4; mt++) {
        int row0 = bm + wm + mt * 16 + g;
        #pragma unroll
        for (int nt = 0; nt < 4; nt++) {
            int col = bn + wn + nt * 8 + 2 * t;
            float bx = bias[col], by = bias[col + 1];
            float2 o0 = make_float2(acc[mt][nt][0] + bx, acc[mt][nt][1] + by);
            float2 o1 = make_float2(acc[mt][nt][2] + bx, acc[mt][nt][3] + by);
            *(float2*)&C[(size_t)row0 * N + col]       = o0;
            *(float2*)&C[(size_t)(row0 + 8) * N + col] = o1;
        }
    }
    #undef STORE_STAGE
    #undef COMPUTE_STAGE
}

// ---------------------------------------------------------------------------
// Kernel 3: windowed attention, 192 threads.
// Scores stored TRANSPOSED: sT[j][i]. AV register-tiles 4x4 over (i, dq):
// per j-step 2x LDS.128 per 16 FMA. Softmax operates on columns of sT.
// ---------------------------------------------------------------------------
#define TOKP 52
#define ATHR 192
__global__ __launch_bounds__(ATHR)
void attn_kernel(float* __restrict__ out) {
    int w = blockIdx.x;
    int h = blockIdx.y;
    __shared__ float qT[HD][TOKP];
    __shared__ float kT[HD][TOKP];
    __shared__ float v[TOK][HD];
    __shared__ float sT[TOKP][TOKP];   // sT[j][i] = S[i][j]

    int tid = threadIdx.x;
    const float scale = 0.17677669529663687f;  // 32^-0.5

    // zero the 3 pad token columns of qT/kT
    for (int i = tid; i < HD * 3; i += ATHR) {
        int dd = i / 3, tp = TOK + i % 3;
        qT[dd][tp] = 0.f;
        kT[dd][tp] = 0.f;
    }

    size_t base = (size_t)w * TOK * QKV_N + (size_t)h * HD;
    for (int i = tid; i < TOK * (HD / 4); i += ATHR) {
        int t = i / (HD / 4), dq = (i % (HD / 4)) * 4;
        const float* row = g_qkv + base + (size_t)t * QKV_N + dq;
        float4 qv = *(const float4*)(row);
        float4 kv = *(const float4*)(row + DIM);
        float4 vv = *(const float4*)(row + 2 * DIM);
        qT[dq + 0][t] = qv.x * scale;
        qT[dq + 1][t] = qv.y * scale;
        qT[dq + 2][t] = qv.z * scale;
        qT[dq + 3][t] = qv.w * scale;
        kT[dq + 0][t] = kv.x;
        kT[dq + 1][t] = kv.y;
        kT[dq + 2][t] = kv.z;
        kT[dq + 3][t] = kv.w;
        *(float4*)&v[t][dq] = vv;
    }
    __syncthreads();

    // scores: 13x13 grid of 4x4 tiles; write transposed sT[j][i]
    const float* bptr = g_bias + h * TOK * TOK;
    if (tid < 169) {
        int i0 = (tid / 13) * 4;
        int j0 = (tid % 13) * 4;
        float acc[4][4];   // [r=i][c=j]
        #pragma unroll
        for (int r = 0; r < 4; r++)
            #pragma unroll
            for (int c = 0; c < 4; c++) acc[r][c] = 0.f;
        #pragma unroll
        for (int dd = 0; dd < HD; dd++) {
            float4 qa = *(const float4*)&qT[dd][i0];
            float4 ka = *(const float4*)&kT[dd][j0];
            float qr[4] = {qa.x, qa.y, qa.z, qa.w};
            float kc[4] = {ka.x, ka.y, ka.z, ka.w};
            #pragma unroll
            for (int r = 0; r < 4; r++)
                #pragma unroll
                for (int c = 0; c < 4; c++)
                    acc[r][c] = fmaf(qr[r], kc[c], acc[r][c]);
        }
        #pragma unroll
        for (int c = 0; c < 4; c++) {
            int j = j0 + c;
            float4 o;
            float b0 = (i0 + 0 < TOK && j < TOK) ? bptr[(i0 + 0) * TOK + j] : 0.f;
            float b1 = (i0 + 1 < TOK && j < TOK) ? bptr[(i0 + 1) * TOK + j] : 0.f;
            float b2 = (i0 + 2 < TOK && j < TOK) ? bptr[(i0 + 2) * TOK + j] : 0.f;
            float b3 = (i0 + 3 < TOK && j < TOK) ? bptr[(i0 + 3) * TOK + j] : 0.f;
            o.x = acc[0][c] + b0;
            o.y = acc[1][c] + b1;
            o.z = acc[2][c] + b2;
            o.w = acc[3][c] + b3;
            *(float4*)&sT[j][i0] = o;   // transposed store
        }
    }
    __syncthreads();

    // softmax: thread i owns column i of sT (= row i of S)
    if (tid < TOK) {
        float mx = -1e30f;
        #pragma unroll 7
        for (int j = 0; j < TOK; j++) mx = fmaxf(mx, sT[j][tid]);
        float sum = 0.f;
        #pragma unroll 7
        for (int j = 0; j < TOK; j++) {
            float e = __expf(sT[j][tid] - mx);
            sT[j][tid] = e;
            sum += e;
        }
        float inv = 1.0f / sum;
        #pragma unroll 7
        for (int j = 0; j < TOK; j++) sT[j][tid] *= inv;
    }
    __syncthreads();

    // AV: thread owns 4x4 tile (i-quad, dq-quad): 13 * 8 = 104 threads
    if (tid < 104) {
        int i0 = (tid >> 3) * 4;          // 0,4,...,48
        int dq = (tid & 7) * 4;           // 0..28
        float acc[4][4];
        #pragma unroll
        for (int r = 0; r < 4; r++)
            #pragma unroll
            for (int c = 0; c < 4; c++) acc[r][c] = 0.f;
        #pragma unroll 7
        for (int j = 0; j < TOK; j++) {
            float4 sa = *(const float4*)&sT[j][i0];
            float4 va = *(const float4*)&v[j][dq];
            float sr[4] = {sa.x, sa.y, sa.z, sa.w};
            float vc[4] = {va.x, va.y, va.z, va.w};
            #pragma unroll
            for (int r = 0; r < 4; r++)
                #pragma unroll
                for (int c = 0; c < 4; c++)
                    acc[r][c] = fmaf(sr[r], vc[c], acc[r][c]);
        }
        #pragma unroll
        for (int r = 0; r < 4; r++) {
            int i = i0 + r;
            if (i < TOK) {
                float4 o = make_float4(acc[r][0], acc[r][1], acc[r][2], acc[r][3]);
                *(float4*)&out[((size_t)w * TOK + i) * DIM + h * HD + dq] = o;
            }
        }
    }
}

// ---------------------------------------------------------------------------
extern "C" void kernel_launch(void* const* d_in, const int* in_sizes, int n_in,
                              void* d_out, int out_size) {
    const float* x       = (const float*)d_in[0];
    const float* qkv_w   = (const float*)d_in[1];
    const float* qkv_b   = (const float*)d_in[2];
    const float* proj_w  = (const float*)d_in[3];
    const float* proj_b  = (const float*)d_in[4];
    const float* table   = (const float*)d_in[5];
    const int*   ridx    = (const int*)d_in[6];
    float*       out     = (float*)d_out;

    float *qkv_buf = nullptr, *att_buf = nullptr;
    cudaGetSymbolAddress((void**)&qkv_buf, g_qkv);
    cudaGetSymbolAddress((void**)&att_buf, g_att);

    {
        int total = TOK * TOK * HEADS;
        bias_kernel<<<(total + 255) / 256, 256>>>(table, ridx);
    }
    {
        dim3 grid(QKV_N / 128, M_TOTAL / 128);   // (9, 784)
        gemm_tf32<<<grid, 256>>>(x, qkv_w, qkv_b, qkv_buf, M_TOTAL, QKV_N, DIM);
    }
    {
        dim3 grid(NWIN, HEADS);                  // (2048, 12)
        attn_kernel<<<grid, ATHR>>>(att_buf);
    }
    {
        dim3 grid(DIM / 128, M_TOTAL / 128);     // (3, 784)
        gemm_tf32<<<grid, 256>>>(att_buf, proj_w, proj_b, out, M_TOTAL, DIM, DIM);
    }
}

// round 8
// speedup vs baseline: 1.8942x; 1.0027x over previous
#include <cuda_runtime.h>
#include <cuda_bf16.h>
#include <cstdint>

#define DIM    384
#define HEADS  12
#define TOK    49
#define HD     32
#define NTOK   3136
#define BATCH  32
#define M_TOTAL (BATCH * NTOK)   // 100352 rows
#define QKV_N  (3 * DIM)         // 1152
#define NWIN   (M_TOTAL / TOK)   // 2048 windows total

// Scratch (static device globals — allocation-free per harness rules)
__device__ float g_qkv[(size_t)M_TOTAL * QKV_N];   // [100352, 1152]
__device__ float g_att[(size_t)M_TOTAL * DIM];     // [100352, 384]
__device__ float g_bias[HEADS * TOK * TOK];        // [12, 49, 49]

// ---------------------------------------------------------------------------
// Kernel 1: gather relative-position bias into [H, 49, 49]
// ---------------------------------------------------------------------------
__global__ void bias_kernel(const float* __restrict__ table,
                            const int* __restrict__ ridx) {
    int i = blockIdx.x * blockDim.x + threadIdx.x;
    if (i < TOK * TOK * HEADS) {
        int h = i % HEADS;
        int p = i / HEADS;
        g_bias[h * TOK * TOK + p] = table[ridx[p] * HEADS + h];
    }
}

// ---------------------------------------------------------------------------
__device__ __forceinline__ unsigned int f2tf(float f) {
    unsigned int r;
    asm("cvt.rna.tf32.f32 %0, %1;" : "=r"(r) : "f"(f));
    return r;
}

// ---------------------------------------------------------------------------
// Kernel 2/4: tf32 tensor-core GEMM, 2-stage smem double buffer (R4 proven).
// C = A[M,K] @ B[K,N] + bias[N]. 128x128 CTA, BK=16, 256 thr, warp 64x32.
// ---------------------------------------------------------------------------
__global__ __launch_bounds__(256)
void gemm_tf32(const float* __restrict__ A, const float* __restrict__ B,
               const float* __restrict__ bias, float* __restrict__ C,
               int M, int N, int K) {
    const int BM = 128, BN = 128, BK = 16;
    __shared__ unsigned int As[2][BK][BM + 8];
    __shared__ unsigned int Bs[2][BK][BN + 8];

    int tid  = threadIdx.x;
    int lane = tid & 31;
    int warp = tid >> 5;
    int wm = (warp >> 2) * 64;
    int wn = (warp & 3) * 32;
    int g = lane >> 2;
    int t = lane & 3;

    int bm = blockIdx.y * BM;
    int bn = blockIdx.x * BN;

    float acc[4][4][4];
    #pragma unroll
    for (int i = 0; i < 4; i++)
        #pragma unroll
        for (int j = 0; j < 4; j++)
            #pragma unroll
            for (int r = 0; r < 4; r++) acc[i][j][r] = 0.f;

    int arow = tid >> 2;
    int aq   = (tid & 3) * 4;
    int brow = tid >> 4;
    int bq   = (tid & 15) * 4;

    const float* Ap0 = A + (size_t)(bm + arow) * K + aq;
    const float* Ap1 = A + (size_t)(bm + arow + 64) * K + aq;

    float4 a0v, a1v, b0v, b1v;

    a0v = *(const float4*)(Ap0);
    a1v = *(const float4*)(Ap1);
    {
        const float* bp = B + (size_t)brow * N + bn;
        b0v = *(const float4*)(bp + bq);
        b1v = *(const float4*)(bp + bq + 64);
    }
    #define STORE_STAGE(buf)                                                  \
        do {                                                                  \
            As[buf][aq + 0][arow]      = f2tf(a0v.x);                         \
            As[buf][aq + 1][arow]      = f2tf(a0v.y);                         \
            As[buf][aq + 2][arow]      = f2tf(a0v.z);                         \
            As[buf][aq + 3][arow]      = f2tf(a0v.w);                         \
            As[buf][aq + 0][arow + 64] = f2tf(a1v.x);                         \
            As[buf][aq + 1][arow + 64] = f2tf(a1v.y);                         \
            As[buf][aq + 2][arow + 64] = f2tf(a1v.z);                         \
            As[buf][aq + 3][arow + 64] = f2tf(a1v.w);                         \
            uint4 u0 = make_uint4(f2tf(b0v.x), f2tf(b0v.y), f2tf(b0v.z), f2tf(b0v.w)); \
            uint4 u1 = make_uint4(f2tf(b1v.x), f2tf(b1v.y), f2tf(b1v.z), f2tf(b1v.w)); \
            *(uint4*)&Bs[buf][brow][bq]      = u0;                            \
            *(uint4*)&Bs[buf][brow][bq + 64] = u1;                            \
        } while (0)

    #define COMPUTE_STAGE(buf)                                                \
        do {                                                                  \
            _Pragma("unroll")                                                 \
            for (int ks = 0; ks < 2; ks++) {                                  \
                int kb = ks * 8;                                              \
                unsigned int af[4][4];                                        \
                unsigned int bf[4][2];                                        \
                _Pragma("unroll")                                             \
                for (int mt = 0; mt < 4; mt++) {                              \
                    int m0 = wm + mt * 16;                                    \
                    af[mt][0] = As[buf][kb + t][m0 + g];                      \
                    af[mt][1] = As[buf][kb + t][m0 + g + 8];                  \
                    af[mt][2] = As[buf][kb + t + 4][m0 + g];                  \
                    af[mt][3] = As[buf][kb + t + 4][m0 + g + 8];              \
                }                                                             \
                _Pragma("unroll")                                             \
                for (int nt = 0; nt < 4; nt++) {                              \
                    int n0 = wn + nt * 8;                                     \
                    bf[nt][0] = Bs[buf][kb + t][n0 + g];                      \
                    bf[nt][1] = Bs[buf][kb + t + 4][n0 + g];                  \
                }                                                             \
                _Pragma("unroll")                                             \
                for (int mt = 0; mt < 4; mt++)                                \
                    _Pragma("unroll")                                         \
                    for (int nt = 0; nt < 4; nt++) {                          \
                        asm volatile(                                         \
                            "mma.sync.aligned.m16n8k8.row.col.f32.tf32.tf32.f32 " \
                            "{%0,%1,%2,%3}, {%4,%5,%6,%7}, {%8,%9}, {%0,%1,%2,%3};" \
                            : "+f"(acc[mt][nt][0]), "+f"(acc[mt][nt][1]),     \
                              "+f"(acc[mt][nt][2]), "+f"(acc[mt][nt][3])      \
                            : "r"(af[mt][0]), "r"(af[mt][1]),                 \
                              "r"(af[mt][2]), "r"(af[mt][3]),                 \
                              "r"(bf[nt][0]), "r"(bf[nt][1]));                \
                    }                                                         \
            }                                                                 \
        } while (0)

    STORE_STAGE(0);
    __syncthreads();

    int cur = 0;
    for (int k0 = BK; k0 < K; k0 += BK) {
        a0v = *(const float4*)(Ap0 + k0);
        a1v = *(const float4*)(Ap1 + k0);
        const float* bp = B + (size_t)(k0 + brow) * N + bn;
        b0v = *(const float4*)(bp + bq);
        b1v = *(const float4*)(bp + bq + 64);
        COMPUTE_STAGE(cur);
        STORE_STAGE(cur ^ 1);
        __syncthreads();
        cur ^= 1;
    }
    COMPUTE_STAGE(cur);

    #pragma unroll
    for (int mt = 0; mt < 4; mt++) {
        int row0 = bm + wm + mt * 16 + g;
        #pragma unroll
        for (int nt = 0; nt < 4; nt++) {
            int col = bn + wn + nt * 8 + 2 * t;
            float bx = bias[col], by = bias[col + 1];
            float2 o0 = make_float2(acc[mt][nt][0] + bx, acc[mt][nt][1] + by);
            float2 o1 = make_float2(acc[mt][nt][2] + bx, acc[mt][nt][3] + by);
            *(float2*)&C[(size_t)row0 * N + col]       = o0;
            *(float2*)&C[(size_t)(row0 + 8) * N + col] = o1;
        }
    }
    #undef STORE_STAGE
    #undef COMPUTE_STAGE
}

// ---------------------------------------------------------------------------
// Kernel 3: windowed attention, 192 threads.
// Scores stored TRANSPOSED: sT[j][i]. AV register-tiles 4x4 over (i, dq):
// per j-step 2x LDS.128 per 16 FMA. Softmax operates on columns of sT.
// ---------------------------------------------------------------------------
#define TOKP 52
#define ATHR 192
__global__ __launch_bounds__(ATHR)
void attn_kernel(float* __restrict__ out) {
    int w = blockIdx.x;
    int h = blockIdx.y;
    __shared__ float qT[HD][TOKP];
    __shared__ float kT[HD][TOKP];
    __shared__ float v[TOK][HD];
    __shared__ float sT[TOKP][TOKP];   // sT[j][i] = S[i][j]

    int tid = threadIdx.x;
    const float scale = 0.17677669529663687f;  // 32^-0.5

    // zero the 3 pad token columns of qT/kT
    for (int i = tid; i < HD * 3; i += ATHR) {
        int dd = i / 3, tp = TOK + i % 3;
        qT[dd][tp] = 0.f;
        kT[dd][tp] = 0.f;
    }

    size_t base = (size_t)w * TOK * QKV_N + (size_t)h * HD;
    for (int i = tid; i < TOK * (HD / 4); i += ATHR) {
        int t = i / (HD / 4), dq = (i % (HD / 4)) * 4;
        const float* row = g_qkv + base + (size_t)t * QKV_N + dq;
        float4 qv = *(const float4*)(row);
        float4 kv = *(const float4*)(row + DIM);
        float4 vv = *(const float4*)(row + 2 * DIM);
        qT[dq + 0][t] = qv.x * scale;
        qT[dq + 1][t] = qv.y * scale;
        qT[dq + 2][t] = qv.z * scale;
        qT[dq + 3][t] = qv.w * scale;
        kT[dq + 0][t] = kv.x;
        kT[dq + 1][t] = kv.y;
        kT[dq + 2][t] = kv.z;
        kT[dq + 3][t] = kv.w;
        *(float4*)&v[t][dq] = vv;
    }
    __syncthreads();

    // scores: 13x13 grid of 4x4 tiles; write transposed sT[j][i]
    const float* bptr = g_bias + h * TOK * TOK;
    if (tid < 169) {
        int i0 = (tid / 13) * 4;
        int j0 = (tid % 13) * 4;
        float acc[4][4];   // [r=i][c=j]
        #pragma unroll
        for (int r = 0; r < 4; r++)
            #pragma unroll
            for (int c = 0; c < 4; c++) acc[r][c] = 0.f;
        #pragma unroll
        for (int dd = 0; dd < HD; dd++) {
            float4 qa = *(const float4*)&qT[dd][i0];
            float4 ka = *(const float4*)&kT[dd][j0];
            float qr[4] = {qa.x, qa.y, qa.z, qa.w};
            float kc[4] = {ka.x, ka.y, ka.z, ka.w};
            #pragma unroll
            for (int r = 0; r < 4; r++)
                #pragma unroll
                for (int c = 0; c < 4; c++)
                    acc[r][c] = fmaf(qr[r], kc[c], acc[r][c]);
        }
        #pragma unroll
        for (int c = 0; c < 4; c++) {
            int j = j0 + c;
            float4 o;
            float b0 = (i0 + 0 < TOK && j < TOK) ? bptr[(i0 + 0) * TOK + j] : 0.f;
            float b1 = (i0 + 1 < TOK && j < TOK) ? bptr[(i0 + 1) * TOK + j] : 0.f;
            float b2 = (i0 + 2 < TOK && j < TOK) ? bptr[(i0 + 2) * TOK + j] : 0.f;
            float b3 = (i0 + 3 < TOK && j < TOK) ? bptr[(i0 + 3) * TOK + j] : 0.f;
            o.x = acc[0][c] + b0;
            o.y = acc[1][c] + b1;
            o.z = acc[2][c] + b2;
            o.w = acc[3][c] + b3;
            *(float4*)&sT[j][i0] = o;   // transposed store
        }
    }
    __syncthreads();

    // softmax: thread i owns column i of sT (= row i of S)
    if (tid < TOK) {
        float mx = -1e30f;
        #pragma unroll 7
        for (int j = 0; j < TOK; j++) mx = fmaxf(mx, sT[j][tid]);
        float sum = 0.f;
        #pragma unroll 7
        for (int j = 0; j < TOK; j++) {
            float e = __expf(sT[j][tid] - mx);
            sT[j][tid] = e;
            sum += e;
        }
        float inv = 1.0f / sum;
        #pragma unroll 7
        for (int j = 0; j < TOK; j++) sT[j][tid] *= inv;
    }
    __syncthreads();

    // AV: thread owns 4x4 tile (i-quad, dq-quad): 13 * 8 = 104 threads
    if (tid < 104) {
        int i0 = (tid >> 3) * 4;          // 0,4,...,48
        int dq = (tid & 7) * 4;           // 0..28
        float acc[4][4];
        #pragma unroll
        for (int r = 0; r < 4; r++)
            #pragma unroll
            for (int c = 0; c < 4; c++) acc[r][c] = 0.f;
        #pragma unroll 7
        for (int j = 0; j < TOK; j++) {
            float4 sa = *(const float4*)&sT[j][i0];
            float4 va = *(const float4*)&v[j][dq];
            float sr[4] = {sa.x, sa.y, sa.z, sa.w};
            float vc[4] = {va.x, va.y, va.z, va.w};
            #pragma unroll
            for (int r = 0; r < 4; r++)
                #pragma unroll
                for (int c = 0; c < 4; c++)
                    acc[r][c] = fmaf(sr[r], vc[c], acc[r][c]);
        }
        #pragma unroll
        for (int r = 0; r < 4; r++) {
            int i = i0 + r;
            if (i < TOK) {
                float4 o = make_float4(acc[r][0], acc[r][1], acc[r][2], acc[r][3]);
                *(float4*)&out[((size_t)w * TOK + i) * DIM + h * HD + dq] = o;
            }
        }
    }
}

// ---------------------------------------------------------------------------
extern "C" void kernel_launch(void* const* d_in, const int* in_sizes, int n_in,
                              void* d_out, int out_size) {
    const float* x       = (const float*)d_in[0];
    const float* qkv_w   = (const float*)d_in[1];
    const float* qkv_b   = (const float*)d_in[2];
    const float* proj_w  = (const float*)d_in[3];
    const float* proj_b  = (const float*)d_in[4];
    const float* table   = (const float*)d_in[5];
    const int*   ridx    = (const int*)d_in[6];
    float*       out     = (float*)d_out;

    float *qkv_buf = nullptr, *att_buf = nullptr;
    cudaGetSymbolAddress((void**)&qkv_buf, g_qkv);
    cudaGetSymbolAddress((void**)&att_buf, g_att);

    {
        int total = TOK * TOK * HEADS;
        bias_kernel<<<(total + 255) / 256, 256>>>(table, ridx);
    }
    {
        dim3 grid(QKV_N / 128, M_TOTAL / 128);   // (9, 784)
        gemm_tf32<<<grid, 256>>>(x, qkv_w, qkv_b, qkv_buf, M_TOTAL, QKV_N, DIM);
    }
    {
        dim3 grid(NWIN, HEADS);                  // (2048, 12)
        attn_kernel<<<grid, ATHR>>>(att_buf);
    }
    {
        dim3 grid(DIM / 128, M_TOTAL / 128);     // (3, 784)
        gemm_tf32<<<grid, 256>>>(att_buf, proj_w, proj_b, out, M_TOTAL, DIM, DIM);
    }
}

// round 9
// speedup vs baseline: 1.8949x; 1.0004x over previous
#include <cuda_runtime.h>
#include <cuda_bf16.h>
#include <cstdint>

#define DIM    384
#define HEADS  12
#define TOK    49
#define HD     32
#define NTOK   3136
#define BATCH  32
#define M_TOTAL (BATCH * NTOK)   // 100352 rows
#define QKV_N  (3 * DIM)         // 1152
#define NWIN   (M_TOTAL / TOK)   // 2048 windows total

// Scratch (static device globals — allocation-free per harness rules)
__device__ float g_qkv[(size_t)M_TOTAL * QKV_N];   // [100352, 1152]
__device__ float g_att[(size_t)M_TOTAL * DIM];     // [100352, 384]
__device__ float g_bias[HEADS * TOK * TOK];        // [12, 49, 49]

// ---------------------------------------------------------------------------
// Kernel 1: gather relative-position bias into [H, 49, 49]
// ---------------------------------------------------------------------------
__global__ void bias_kernel(const float* __restrict__ table,
                            const int* __restrict__ ridx) {
    int i = blockIdx.x * blockDim.x + threadIdx.x;
    if (i < TOK * TOK * HEADS) {
        int h = i % HEADS;
        int p = i / HEADS;
        g_bias[h * TOK * TOK + p] = table[ridx[p] * HEADS + h];
    }
}

// ---------------------------------------------------------------------------
__device__ __forceinline__ unsigned int f2tf(float f) {
    unsigned int r;
    asm("cvt.rna.tf32.f32 %0, %1;" : "=r"(r) : "f"(f));
    return r;
}

// ---------------------------------------------------------------------------
// Kernel 2/4: tf32 tensor-core GEMM, 2-stage smem double buffer (R4 proven).
// C = A[M,K] @ B[K,N] + bias[N]. 128x128 CTA, BK=16, 256 thr, warp 64x32.
// ---------------------------------------------------------------------------
__global__ __launch_bounds__(256)
void gemm_tf32(const float* __restrict__ A, const float* __restrict__ B,
               const float* __restrict__ bias, float* __restrict__ C,
               int M, int N, int K) {
    const int BM = 128, BN = 128, BK = 16;
    __shared__ unsigned int As[2][BK][BM + 8];
    __shared__ unsigned int Bs[2][BK][BN + 8];

    int tid  = threadIdx.x;
    int lane = tid & 31;
    int warp = tid >> 5;
    int wm = (warp >> 2) * 64;
    int wn = (warp & 3) * 32;
    int g = lane >> 2;
    int t = lane & 3;

    int bm = blockIdx.y * BM;
    int bn = blockIdx.x * BN;

    float acc[4][4][4];
    #pragma unroll
    for (int i = 0; i < 4; i++)
        #pragma unroll
        for (int j = 0; j < 4; j++)
            #pragma unroll
            for (int r = 0; r < 4; r++) acc[i][j][r] = 0.f;

    int arow = tid >> 2;
    int aq   = (tid & 3) * 4;
    int brow = tid >> 4;
    int bq   = (tid & 15) * 4;

    const float* Ap0 = A + (size_t)(bm + arow) * K + aq;
    const float* Ap1 = A + (size_t)(bm + arow + 64) * K + aq;

    float4 a0v, a1v, b0v, b1v;

    a0v = *(const float4*)(Ap0);
    a1v = *(const float4*)(Ap1);
    {
        const float* bp = B + (size_t)brow * N + bn;
        b0v = *(const float4*)(bp + bq);
        b1v = *(const float4*)(bp + bq + 64);
    }
    #define STORE_STAGE(buf)                                                  \
        do {                                                                  \
            As[buf][aq + 0][arow]      = f2tf(a0v.x);                         \
            As[buf][aq + 1][arow]      = f2tf(a0v.y);                         \
            As[buf][aq + 2][arow]      = f2tf(a0v.z);                         \
            As[buf][aq + 3][arow]      = f2tf(a0v.w);                         \
            As[buf][aq + 0][arow + 64] = f2tf(a1v.x);                         \
            As[buf][aq + 1][arow + 64] = f2tf(a1v.y);                         \
            As[buf][aq + 2][arow + 64] = f2tf(a1v.z);                         \
            As[buf][aq + 3][arow + 64] = f2tf(a1v.w);                         \
            uint4 u0 = make_uint4(f2tf(b0v.x), f2tf(b0v.y), f2tf(b0v.z), f2tf(b0v.w)); \
            uint4 u1 = make_uint4(f2tf(b1v.x), f2tf(b1v.y), f2tf(b1v.z), f2tf(b1v.w)); \
            *(uint4*)&Bs[buf][brow][bq]      = u0;                            \
            *(uint4*)&Bs[buf][brow][bq + 64] = u1;                            \
        } while (0)

    #define COMPUTE_STAGE(buf)                                                \
        do {                                                                  \
            _Pragma("unroll")                                                 \
            for (int ks = 0; ks < 2; ks++) {                                  \
                int kb = ks * 8;                                              \
                unsigned int af[4][4];                                        \
                unsigned int bf[4][2];                                        \
                _Pragma("unroll")                                             \
                for (int mt = 0; mt < 4; mt++) {                              \
                    int m0 = wm + mt * 16;                                    \
                    af[mt][0] = As[buf][kb + t][m0 + g];                      \
                    af[mt][1] = As[buf][kb + t][m0 + g + 8];                  \
                    af[mt][2] = As[buf][kb + t + 4][m0 + g];                  \
                    af[mt][3] = As[buf][kb + t + 4][m0 + g + 8];              \
                }                                                             \
                _Pragma("unroll")                                             \
                for (int nt = 0; nt < 4; nt++) {                              \
                    int n0 = wn + nt * 8;                                     \
                    bf[nt][0] = Bs[buf][kb + t][n0 + g];                      \
                    bf[nt][1] = Bs[buf][kb + t + 4][n0 + g];                  \
                }                                                             \
                _Pragma("unroll")                                             \
                for (int mt = 0; mt < 4; mt++)                                \
                    _Pragma("unroll")                                         \
                    for (int nt = 0; nt < 4; nt++) {                          \
                        asm volatile(                                         \
                            "mma.sync.aligned.m16n8k8.row.col.f32.tf32.tf32.f32 " \
                            "{%0,%1,%2,%3}, {%4,%5,%6,%7}, {%8,%9}, {%0,%1,%2,%3};" \
                            : "+f"(acc[mt][nt][0]), "+f"(acc[mt][nt][1]),     \
                              "+f"(acc[mt][nt][2]), "+f"(acc[mt][nt][3])      \
                            : "r"(af[mt][0]), "r"(af[mt][1]),                 \
                              "r"(af[mt][2]), "r"(af[mt][3]),                 \
                              "r"(bf[nt][0]), "r"(bf[nt][1]));                \
                    }                                                         \
            }                                                                 \
        } while (0)

    STORE_STAGE(0);
    __syncthreads();

    int cur = 0;
    for (int k0 = BK; k0 < K; k0 += BK) {
        a0v = *(const float4*)(Ap0 + k0);
        a1v = *(const float4*)(Ap1 + k0);
        const float* bp = B + (size_t)(k0 + brow) * N + bn;
        b0v = *(const float4*)(bp + bq);
        b1v = *(const float4*)(bp + bq + 64);
        COMPUTE_STAGE(cur);
        STORE_STAGE(cur ^ 1);
        __syncthreads();
        cur ^= 1;
    }
    COMPUTE_STAGE(cur);

    #pragma unroll
    for (int mt = 0; mt < 4; mt++) {
        int row0 = bm + wm + mt * 16 + g;
        #pragma unroll
        for (int nt = 0; nt < 4; nt++) {
            int col = bn + wn + nt * 8 + 2 * t;
            float bx = bias[col], by = bias[col + 1];
            float2 o0 = make_float2(acc[mt][nt][0] + bx, acc[mt][nt][1] + by);
            float2 o1 = make_float2(acc[mt][nt][2] + bx, acc[mt][nt][3] + by);
            *(float2*)&C[(size_t)row0 * N + col]       = o0;
            *(float2*)&C[(size_t)(row0 + 8) * N + col] = o1;
        }
    }
    #undef STORE_STAGE
    #undef COMPUTE_STAGE
}

// ---------------------------------------------------------------------------
// Kernel 3: windowed attention, 192 threads.
// Scores stored TRANSPOSED: sT[j][i]. AV register-tiles 4x4 over (i, dq):
// per j-step 2x LDS.128 per 16 FMA. Softmax operates on columns of sT.
// ---------------------------------------------------------------------------
#define TOKP 52
#define ATHR 192
__global__ __launch_bounds__(ATHR)
void attn_kernel(float* __restrict__ out) {
    int w = blockIdx.x;
    int h = blockIdx.y;
    __shared__ float qT[HD][TOKP];
    __shared__ float kT[HD][TOKP];
    __shared__ float v[TOK][HD];
    __shared__ float sT[TOKP][TOKP];   // sT[j][i] = S[i][j]

    int tid = threadIdx.x;
    const float scale = 0.17677669529663687f;  // 32^-0.5

    // zero the 3 pad token columns of qT/kT
    for (int i = tid; i < HD * 3; i += ATHR) {
        int dd = i / 3, tp = TOK + i % 3;
        qT[dd][tp] = 0.f;
        kT[dd][tp] = 0.f;
    }

    size_t base = (size_t)w * TOK * QKV_N + (size_t)h * HD;
    for (int i = tid; i < TOK * (HD / 4); i += ATHR) {
        int t = i / (HD / 4), dq = (i % (HD / 4)) * 4;
        const float* row = g_qkv + base + (size_t)t * QKV_N + dq;
        float4 qv = *(const float4*)(row);
        float4 kv = *(const float4*)(row + DIM);
        float4 vv = *(const float4*)(row + 2 * DIM);
        qT[dq + 0][t] = qv.x * scale;
        qT[dq + 1][t] = qv.y * scale;
        qT[dq + 2][t] = qv.z * scale;
        qT[dq + 3][t] = qv.w * scale;
        kT[dq + 0][t] = kv.x;
        kT[dq + 1][t] = kv.y;
        kT[dq + 2][t] = kv.z;
        kT[dq + 3][t] = kv.w;
        *(float4*)&v[t][dq] = vv;
    }
    __syncthreads();

    // scores: 13x13 grid of 4x4 tiles; write transposed sT[j][i]
    const float* bptr = g_bias + h * TOK * TOK;
    if (tid < 169) {
        int i0 = (tid / 13) * 4;
        int j0 = (tid % 13) * 4;
        float acc[4][4];   // [r=i][c=j]
        #pragma unroll
        for (int r = 0; r < 4; r++)
            #pragma unroll
            for (int c = 0; c < 4; c++) acc[r][c] = 0.f;
        #pragma unroll
        for (int dd = 0; dd < HD; dd++) {
            float4 qa = *(const float4*)&qT[dd][i0];
            float4 ka = *(const float4*)&kT[dd][j0];
            float qr[4] = {qa.x, qa.y, qa.z, qa.w};
            float kc[4] = {ka.x, ka.y, ka.z, ka.w};
            #pragma unroll
            for (int r = 0; r < 4; r++)
                #pragma unroll
                for (int c = 0; c < 4; c++)
                    acc[r][c] = fmaf(qr[r], kc[c], acc[r][c]);
        }
        #pragma unroll
        for (int c = 0; c < 4; c++) {
            int j = j0 + c;
            float4 o;
            float b0 = (i0 + 0 < TOK && j < TOK) ? bptr[(i0 + 0) * TOK + j] : 0.f;
            float b1 = (i0 + 1 < TOK && j < TOK) ? bptr[(i0 + 1) * TOK + j] : 0.f;
            float b2 = (i0 + 2 < TOK && j < TOK) ? bptr[(i0 + 2) * TOK + j] : 0.f;
            float b3 = (i0 + 3 < TOK && j < TOK) ? bptr[(i0 + 3) * TOK + j] : 0.f;
            o.x = acc[0][c] + b0;
            o.y = acc[1][c] + b1;
            o.z = acc[2][c] + b2;
            o.w = acc[3][c] + b3;
            *(float4*)&sT[j][i0] = o;   // transposed store
        }
    }
    __syncthreads();

    // softmax: thread i owns column i of sT (= row i of S)
    if (tid < TOK) {
        float mx = -1e30f;
        #pragma unroll 7
        for (int j = 0; j < TOK; j++) mx = fmaxf(mx, sT[j][tid]);
        float sum = 0.f;
        #pragma unroll 7
        for (int j = 0; j < TOK; j++) {
            float e = __expf(sT[j][tid] - mx);
            sT[j][tid] = e;
            sum += e;
        }
        float inv = 1.0f / sum;
        #pragma unroll 7
        for (int j = 0; j < TOK; j++) sT[j][tid] *= inv;
    }
    __syncthreads();

    // AV: thread owns 4x4 tile (i-quad, dq-quad): 13 * 8 = 104 threads
    if (tid < 104) {
        int i0 = (tid >> 3) * 4;          // 0,4,...,48
        int dq = (tid & 7) * 4;           // 0..28
        float acc[4][4];
        #pragma unroll
        for (int r = 0; r < 4; r++)
            #pragma unroll
            for (int c = 0; c < 4; c++) acc[r][c] = 0.f;
        #pragma unroll 7
        for (int j = 0; j < TOK; j++) {
            float4 sa = *(const float4*)&sT[j][i0];
            float4 va = *(const float4*)&v[j][dq];
            float sr[4] = {sa.x, sa.y, sa.z, sa.w};
            float vc[4] = {va.x, va.y, va.z, va.w};
            #pragma unroll
            for (int r = 0; r < 4; r++)
                #pragma unroll
                for (int c = 0; c < 4; c++)
                    acc[r][c] = fmaf(sr[r], vc[c], acc[r][c]);
        }
        #pragma unroll
        for (int r = 0; r < 4; r++) {
            int i = i0 + r;
            if (i < TOK) {
                float4 o = make_float4(acc[r][0], acc[r][1], acc[r][2], acc[r][3]);
                *(float4*)&out[((size_t)w * TOK + i) * DIM + h * HD + dq] = o;
            }
        }
    }
}

// ---------------------------------------------------------------------------
extern "C" void kernel_launch(void* const* d_in, const int* in_sizes, int n_in,
                              void* d_out, int out_size) {
    const float* x       = (const float*)d_in[0];
    const float* qkv_w   = (const float*)d_in[1];
    const float* qkv_b   = (const float*)d_in[2];
    const float* proj_w  = (const float*)d_in[3];
    const float* proj_b  = (const float*)d_in[4];
    const float* table   = (const float*)d_in[5];
    const int*   ridx    = (const int*)d_in[6];
    float*       out     = (float*)d_out;

    float *qkv_buf = nullptr, *att_buf = nullptr;
    cudaGetSymbolAddress((void**)&qkv_buf, g_qkv);
    cudaGetSymbolAddress((void**)&att_buf, g_att);

    {
        int total = TOK * TOK * HEADS;
        bias_kernel<<<(total + 255) / 256, 256>>>(table, ridx);
    }
    {
        dim3 grid(QKV_N / 128, M_TOTAL / 128);   // (9, 784)
        gemm_tf32<<<grid, 256>>>(x, qkv_w, qkv_b, qkv_buf, M_TOTAL, QKV_N, DIM);
    }
    {
        dim3 grid(NWIN, HEADS);                  // (2048, 12)
        attn_kernel<<<grid, ATHR>>>(att_buf);
    }
    {
        dim3 grid(DIM / 128, M_TOTAL / 128);     // (3, 784)
        gemm_tf32<<<grid, 256>>>(att_buf, proj_w, proj_b, out, M_TOTAL, DIM, DIM);
    }
}

// round 11
// speedup vs baseline: 1.9919x; 1.0512x over previous
#include <cuda_runtime.h>
#include <cuda_bf16.h>
#include <cstdint>

#define DIM    384
#define HEADS  12
#define TOK    49
#define HD     32
#define NTOK   3136
#define BATCH  32
#define M_TOTAL (BATCH * NTOK)   // 100352 rows
#define QKV_N  (3 * DIM)         // 1152
#define NWIN   (M_TOTAL / TOK)   // 2048 windows total

// Scratch (static device globals — allocation-free per harness rules)
__device__ float g_x  [(size_t)M_TOTAL * DIM];     // tf32-rounded x
__device__ float g_w1t[QKV_N * DIM];               // qkv_w transposed [N][K], tf32
__device__ float g_w2t[DIM * DIM];                 // proj_w transposed [N][K], tf32
__device__ float g_qkv[(size_t)M_TOTAL * QKV_N];   // [100352, 1152]
__device__ float g_att[(size_t)M_TOTAL * DIM];     // [100352, 384] tf32-rounded
__device__ float g_bias[HEADS * TOK * TOK];        // [12, 49, 49]

// ---------------------------------------------------------------------------
__device__ __forceinline__ unsigned int f2tf(float f) {
    unsigned int r;
    asm("cvt.rna.tf32.f32 %0, %1;" : "=r"(r) : "f"(f));
    return r;
}
__device__ __forceinline__ float f2tff(float f) {
    return __uint_as_float(f2tf(f));
}

// ---------------------------------------------------------------------------
// Kernel 0a: elementwise tf32 rounding
// ---------------------------------------------------------------------------
__global__ void round_tf32(const float* __restrict__ in, float* __restrict__ out,
                           int n4) {
    int i = blockIdx.x * blockDim.x + threadIdx.x;
    if (i < n4) {
        float4 v = ((const float4*)in)[i];
        v.x = f2tff(v.x); v.y = f2tff(v.y); v.z = f2tff(v.z); v.w = f2tff(v.w);
        ((float4*)out)[i] = v;
    }
}

// ---------------------------------------------------------------------------
// Kernel 0b: transpose + tf32 round. in [R][C] -> out [C][R]
// ---------------------------------------------------------------------------
__global__ void transpose_round(const float* __restrict__ in,
                                float* __restrict__ out, int R, int C) {
    __shared__ float tile[32][33];
    int bx = blockIdx.x * 32;   // C offset
    int by = blockIdx.y * 32;   // R offset
    int x = threadIdx.x, y = threadIdx.y;  // 32 x 8
    #pragma unroll
    for (int j = 0; j < 32; j += 8)
        tile[y + j][x] = in[(size_t)(by + y + j) * C + bx + x];
    __syncthreads();
    #pragma unroll
    for (int j = 0; j < 32; j += 8)
        out[(size_t)(bx + y + j) * R + by + x] = f2tff(tile[x][y + j]);
}

// ---------------------------------------------------------------------------
// Kernel 1: gather relative-position bias into [H, 49, 49]
// ---------------------------------------------------------------------------
__global__ void bias_kernel(const float* __restrict__ table,
                            const int* __restrict__ ridx) {
    int i = blockIdx.x * blockDim.x + threadIdx.x;
    if (i < TOK * TOK * HEADS) {
        int h = i % HEADS;
        int p = i / HEADS;
        g_bias[h * TOK * TOK + p] = table[ridx[p] * HEADS + h];
    }
}

// ---------------------------------------------------------------------------
// Kernel 2/4: tf32 mma.sync GEMM, cp.async 3-stage, ldmatrix fragments.
// C[M,N] = A[M,K] @ BT[N,K]^T + bias[N].  A, BT must be tf32-pre-rounded.
// CTA 128x128, BK=32, 256 thr (8 warps, warp tile 64x32), 1 sync per K-tile.
// Smem tile: A[128][32]f + B(=BT rows)[128][32]f per stage, 16B-chunk XOR
// swizzle: chunk' = chunk ^ (row & 7). 3 stages x 32KB = 96KB dynamic.
// ---------------------------------------------------------------------------
#define GEMM_DYN_BYTES (3 * 32768 + 128)

#define LDSM4(R0, R1, R2, R3, ADDR)                                           \
    asm volatile("ldmatrix.sync.aligned.m8n8.x4.shared.b16 {%0,%1,%2,%3}, [%4];" \
                 : "=r"(R0), "=r"(R1), "=r"(R2), "=r"(R3) : "r"(ADDR))
#define LDSM2(R0, R1, ADDR)                                                   \
    asm volatile("ldmatrix.sync.aligned.m8n8.x2.shared.b16 {%0,%1}, [%2];"    \
                 : "=r"(R0), "=r"(R1) : "r"(ADDR))

__global__ __launch_bounds__(256)
void gemm_tf32(const float* __restrict__ A, const float* __restrict__ BT,
               const float* __restrict__ bias, float* __restrict__ C,
               int M, int N, int K) {
    extern __shared__ char dynraw[];
    unsigned int smem_u = (unsigned int)__cvta_generic_to_shared(dynraw);
    smem_u = (smem_u + 127u) & ~127u;

    int tid  = threadIdx.x;
    int lane = tid & 31;
    int warp = tid >> 5;
    int wm = (warp >> 2) * 64;   // warp m offset (0 or 64)
    int wn = (warp & 3) * 32;    // warp n offset (0,32,64,96)
    int g = lane >> 2;           // 0..7
    int t = lane & 3;            // 0..3

    int bm = blockIdx.y * 128;
    int bn = blockIdx.x * 128;
    const float* Ap = A  + (size_t)bm * K;
    const float* Bp = BT + (size_t)bn * K;

    float acc[4][4][4];
    #pragma unroll
    for (int i = 0; i < 4; i++)
        #pragma unroll
        for (int j = 0; j < 4; j++)
            #pragma unroll
            for (int r = 0; r < 4; r++) acc[i][j][r] = 0.f;

    // ldmatrix per-lane row addressing
    int mi = lane >> 3;          // 0..3 (matrix index for x4)
    int rr = lane & 7;           // row within 8-row matrix
    unsigned int aRowOff[4], bRowOff[4];
    #pragma unroll
    for (int mt = 0; mt < 4; mt++)
        aRowOff[mt] = (unsigned int)(wm + mt * 16 + (mi & 1) * 8 + rr) * 128u;
    #pragma unroll
    for (int nt = 0; nt < 4; nt++)
        bRowOff[nt] = (unsigned int)(wn + nt * 8 + rr) * 128u;
    int aCsel = mi >> 1;         // 0/1: chunk select for x4 matrices 2,3
    int bCsel = mi & 1;          // x2 uses lanes 0..15: mi in {0,1}

    // cp.async loader: one 128x32f tile (A) + one (B) per stage.
    // 1024 16B-chunks each; thread covers chunk ca = i*256 + tid, i=0..3.
    #define LOAD_TILE(buf, k0)                                                \
        do {                                                                  \
            unsigned int sA = smem_u + (unsigned int)(buf) * 32768u;          \
            _Pragma("unroll")                                                 \
            for (int i = 0; i < 4; i++) {                                     \
                int ca  = i * 256 + tid;                                      \
                int row = ca >> 3;                                            \
                int ch  = ca & 7;                                             \
                unsigned int d = sA + (unsigned int)row * 128u                \
                                 + (unsigned int)((ch ^ (row & 7)) << 4);     \
                const float* gsa = Ap + (size_t)row * K + (k0) + ch * 4;      \
                const float* gsb = Bp + (size_t)row * K + (k0) + ch * 4;      \
                asm volatile("cp.async.cg.shared.global [%0], [%1], 16;"      \
                             :: "r"(d), "l"(gsa));                            \
                asm volatile("cp.async.cg.shared.global [%0], [%1], 16;"      \
                             :: "r"(d + 16384u), "l"(gsb));                   \
            }                                                                 \
            asm volatile("cp.async.commit_group;");                          \
        } while (0)

    #define COMPUTE_TILE(buf)                                                 \
        do {                                                                  \
            unsigned int sA = smem_u + (unsigned int)(buf) * 32768u;          \
            unsigned int sB = sA + 16384u;                                    \
            _Pragma("unroll")                                                 \
            for (int ks = 0; ks < 4; ks++) {                                  \
                int c0 = 2 * ks;                                              \
                unsigned int af[4][4];                                        \
                unsigned int bf[4][2];                                        \
                _Pragma("unroll")                                             \
                for (int mt = 0; mt < 4; mt++) {                              \
                    unsigned int ad = sA + aRowOff[mt]                        \
                        + (unsigned int)((((c0 + aCsel) ^ rr)) << 4);         \
                    LDSM4(af[mt][0], af[mt][1], af[mt][2], af[mt][3], ad);    \
                }                                                             \
                _Pragma("unroll")                                             \
                for (int nt = 0; nt < 4; nt++) {                              \
                    unsigned int bd = sB + bRowOff[nt]                        \
                        + (unsigned int)((((c0 + bCsel) ^ rr)) << 4);         \
                    LDSM2(bf[nt][0], bf[nt][1], bd);                          \
                }                                                             \
                _Pragma("unroll")                                             \
                for (int mt = 0; mt < 4; mt++)                                \
                    _Pragma("unroll")                                         \
                    for (int nt = 0; nt < 4; nt++) {                          \
                        asm volatile(                                         \
                            "mma.sync.aligned.m16n8k8.row.col.f32.tf32.tf32.f32 " \
                            "{%0,%1,%2,%3}, {%4,%5,%6,%7}, {%8,%9}, {%0,%1,%2,%3};" \
                            : "+f"(acc[mt][nt][0]), "+f"(acc[mt][nt][1]),     \
                              "+f"(acc[mt][nt][2]), "+f"(acc[mt][nt][3])      \
                            : "r"(af[mt][0]), "r"(af[mt][1]),                 \
                              "r"(af[mt][2]), "r"(af[mt][3]),                 \
                              "r"(bf[nt][0]), "r"(bf[nt][1]));                \
                    }                                                         \
            }                                                                 \
        } while (0)

    int T = K / 32;              // 12 for K=384

    LOAD_TILE(0, 0);
    LOAD_TILE(1, 32);

    for (int tt = 0; tt < T; tt++) {
        if (tt < T - 1) {
            asm volatile("cp.async.wait_group 1;");
        } else {
            asm volatile("cp.async.wait_group 0;");
        }
        __syncthreads();
        if (tt + 2 < T) {
            int nb = (tt + 2) % 3;
            LOAD_TILE(nb, (tt + 2) * 32);
        }
        COMPUTE_TILE(tt % 3);
    }
    #undef LOAD_TILE
    #undef COMPUTE_TILE

    // epilogue: c0:(g,2t) c1:(g,2t+1) c2:(g+8,2t) c3:(g+8,2t+1)
    #pragma unroll
    for (int mt = 0; mt < 4; mt++) {
        int row0 = bm + wm + mt * 16 + g;
        #pragma unroll
        for (int nt = 0; nt < 4; nt++) {
            int col = bn + wn + nt * 8 + 2 * t;
            float bx = bias[col], by = bias[col + 1];
            float2 o0 = make_float2(acc[mt][nt][0] + bx, acc[mt][nt][1] + by);
            float2 o1 = make_float2(acc[mt][nt][2] + bx, acc[mt][nt][3] + by);
            *(float2*)&C[(size_t)row0 * N + col]       = o0;
            *(float2*)&C[(size_t)(row0 + 8) * N + col] = o1;
        }
    }
}

// ---------------------------------------------------------------------------
// Kernel 3: windowed attention (R9 proven), output rounded to tf32.
// ---------------------------------------------------------------------------
#define TOKP 52
#define ATHR 192
__global__ __launch_bounds__(ATHR)
void attn_kernel(float* __restrict__ out) {
    int w = blockIdx.x;
    int h = blockIdx.y;
    __shared__ float qT[HD][TOKP];
    __shared__ float kT[HD][TOKP];
    __shared__ float v[TOK][HD];
    __shared__ float sT[TOKP][TOKP];   // sT[j][i] = S[i][j]

    int tid = threadIdx.x;
    const float scale = 0.17677669529663687f;  // 32^-0.5

    for (int i = tid; i < HD * 3; i += ATHR) {
        int dd = i / 3, tp = TOK + i % 3;
        qT[dd][tp] = 0.f;
        kT[dd][tp] = 0.f;
    }

    size_t base = (size_t)w * TOK * QKV_N + (size_t)h * HD;
    for (int i = tid; i < TOK * (HD / 4); i += ATHR) {
        int t = i / (HD / 4), dq = (i % (HD / 4)) * 4;
        const float* row = g_qkv + base + (size_t)t * QKV_N + dq;
        float4 qv = *(const float4*)(row);
        float4 kv = *(const float4*)(row + DIM);
        float4 vv = *(const float4*)(row + 2 * DIM);
        qT[dq + 0][t] = qv.x * scale;
        qT[dq + 1][t] = qv.y * scale;
        qT[dq + 2][t] = qv.z * scale;
        qT[dq + 3][t] = qv.w * scale;
        kT[dq + 0][t] = kv.x;
        kT[dq + 1][t] = kv.y;
        kT[dq + 2][t] = kv.z;
        kT[dq + 3][t] = kv.w;
        *(float4*)&v[t][dq] = vv;
    }
    __syncthreads();

    const float* bptr = g_bias + h * TOK * TOK;
    if (tid < 169) {
        int i0 = (tid / 13) * 4;
        int j0 = (tid % 13) * 4;
        float acc[4][4];
        #pragma unroll
        for (int r = 0; r < 4; r++)
            #pragma unroll
            for (int c = 0; c < 4; c++) acc[r][c] = 0.f;
        #pragma unroll
        for (int dd = 0; dd < HD; dd++) {
            float4 qa = *(const float4*)&qT[dd][i0];
            float4 ka = *(const float4*)&kT[dd][j0];
            float qr[4] = {qa.x, qa.y, qa.z, qa.w};
            float kc[4] = {ka.x, ka.y, ka.z, ka.w};
            #pragma unroll
            for (int r = 0; r < 4; r++)
                #pragma unroll
                for (int c = 0; c < 4; c++)
                    acc[r][c] = fmaf(qr[r], kc[c], acc[r][c]);
        }
        #pragma unroll
        for (int c = 0; c < 4; c++) {
            int j = j0 + c;
            float4 o;
            float b0 = (i0 + 0 < TOK && j < TOK) ? bptr[(i0 + 0) * TOK + j] : 0.f;
            float b1 = (i0 + 1 < TOK && j < TOK) ? bptr[(i0 + 1) * TOK + j] : 0.f;
            float b2 = (i0 + 2 < TOK && j < TOK) ? bptr[(i0 + 2) * TOK + j] : 0.f;
            float b3 = (i0 + 3 < TOK && j < TOK) ? bptr[(i0 + 3) * TOK + j] : 0.f;
            o.x = acc[0][c] + b0;
            o.y = acc[1][c] + b1;
            o.z = acc[2][c] + b2;
            o.w = acc[3][c] + b3;
            *(float4*)&sT[j][i0] = o;
        }
    }
    __syncthreads();

    if (tid < TOK) {
        float mx = -1e30f;
        #pragma unroll 7
        for (int j = 0; j < TOK; j++) mx = fmaxf(mx, sT[j][tid]);
        float sum = 0.f;
        #pragma unroll 7
        for (int j = 0; j < TOK; j++) {
            float e = __expf(sT[j][tid] - mx);
            sT[j][tid] = e;
            sum += e;
        }
        float inv = 1.0f / sum;
        #pragma unroll 7
        for (int j = 0; j < TOK; j++) sT[j][tid] *= inv;
    }
    __syncthreads();

    if (tid < 104) {
        int i0 = (tid >> 3) * 4;
        int dq = (tid & 7) * 4;
        float acc[4][4];
        #pragma unroll
        for (int r = 0; r < 4; r++)
            #pragma unroll
            for (int c = 0; c < 4; c++) acc[r][c] = 0.f;
        #pragma unroll 7
        for (int j = 0; j < TOK; j++) {
            float4 sa = *(const float4*)&sT[j][i0];
            float4 va = *(const float4*)&v[j][dq];
            float sr[4] = {sa.x, sa.y, sa.z, sa.w};
            float vc[4] = {va.x, va.y, va.z, va.w};
            #pragma unroll
            for (int r = 0; r < 4; r++)
                #pragma unroll
                for (int c = 0; c < 4; c++)
                    acc[r][c] = fmaf(sr[r], vc[c], acc[r][c]);
        }
        #pragma unroll
        for (int r = 0; r < 4; r++) {
            int i = i0 + r;
            if (i < TOK) {
                float4 o = make_float4(f2tff(acc[r][0]), f2tff(acc[r][1]),
                                       f2tff(acc[r][2]), f2tff(acc[r][3]));
                *(float4*)&out[((size_t)w * TOK + i) * DIM + h * HD + dq] = o;
            }
        }
    }
}

// ---------------------------------------------------------------------------
extern "C" void kernel_launch(void* const* d_in, const int* in_sizes, int n_in,
                              void* d_out, int out_size) {
    const float* x       = (const float*)d_in[0];
    const float* qkv_w   = (const float*)d_in[1];
    const float* qkv_b   = (const float*)d_in[2];
    const float* proj_w  = (const float*)d_in[3];
    const float* proj_b  = (const float*)d_in[4];
    const float* table   = (const float*)d_in[5];
    const int*   ridx    = (const int*)d_in[6];
    float*       out     = (float*)d_out;

    float *xr = nullptr, *w1t = nullptr, *w2t = nullptr;
    float *qkv_buf = nullptr, *att_buf = nullptr;
    cudaGetSymbolAddress((void**)&xr, g_x);
    cudaGetSymbolAddress((void**)&w1t, g_w1t);
    cudaGetSymbolAddress((void**)&w2t, g_w2t);
    cudaGetSymbolAddress((void**)&qkv_buf, g_qkv);
    cudaGetSymbolAddress((void**)&att_buf, g_att);

    cudaFuncSetAttribute(gemm_tf32, cudaFuncAttributeMaxDynamicSharedMemorySize,
                         GEMM_DYN_BYTES);

    // 0. round x; transpose+round weights; bias gather
    {
        int n4 = (M_TOTAL * DIM) / 4;
        round_tf32<<<(n4 + 255) / 256, 256>>>(x, xr, n4);
        dim3 blk(32, 8);
        transpose_round<<<dim3(QKV_N / 32, DIM / 32), blk>>>(qkv_w, w1t, DIM, QKV_N);
        transpose_round<<<dim3(DIM / 32, DIM / 32), blk>>>(proj_w, w2t, DIM, DIM);
        int total = TOK * TOK * HEADS;
        bias_kernel<<<(total + 255) / 256, 256>>>(table, ridx);
    }
    // 2. QKV GEMM: [100352,384] @ [384,1152] + qkv_b
    {
        dim3 grid(QKV_N / 128, M_TOTAL / 128);   // (9, 784)
        gemm_tf32<<<grid, 256, GEMM_DYN_BYTES>>>(xr, w1t, qkv_b, qkv_buf,
                                                 M_TOTAL, QKV_N, DIM);
    }
    // 3. window attention
    {
        dim3 grid(NWIN, HEADS);                  // (2048, 12)
        attn_kernel<<<grid, ATHR>>>(att_buf);
    }
    // 4. proj GEMM: [100352,384] @ [384,384] + proj_b -> d_out
    {
        dim3 grid(DIM / 128, M_TOTAL / 128);     // (3, 784)
        gemm_tf32<<<grid, 256, GEMM_DYN_BYTES>>>(att_buf, w2t, proj_b, out,
                                                 M_TOTAL, DIM, DIM);
    }
}

// round 12
// speedup vs baseline: 2.4812x; 1.2457x over previous
#include <cuda_runtime.h>
#include <cuda_bf16.h>
#include <cstdint>

#define DIM    384
#define HEADS  12
#define TOK    49
#define HD     32
#define NTOK   3136
#define BATCH  32
#define M_TOTAL (BATCH * NTOK)   // 100352 rows
#define QKV_N  (3 * DIM)         // 1152
#define NWIN   (M_TOTAL / TOK)   // 2048 windows total

// Scratch (static device globals — allocation-free per harness rules)
__device__ float g_x  [(size_t)M_TOTAL * DIM];     // tf32-rounded x
__device__ float g_w1t[QKV_N * DIM];               // qkv_w transposed [N][K], tf32
__device__ float g_w2t[DIM * DIM];                 // proj_w transposed [N][K], tf32
__device__ float g_qkv[(size_t)M_TOTAL * QKV_N];   // [100352, 1152]
__device__ float g_att[(size_t)M_TOTAL * DIM];     // [100352, 384] tf32-rounded
__device__ float g_bias[HEADS * TOK * TOK];        // [12, 49, 49]

// ---------------------------------------------------------------------------
__device__ __forceinline__ unsigned int f2tf(float f) {
    unsigned int r;
    asm("cvt.rna.tf32.f32 %0, %1;" : "=r"(r) : "f"(f));
    return r;
}
__device__ __forceinline__ float f2tff(float f) {
    return __uint_as_float(f2tf(f));
}

// ---------------------------------------------------------------------------
// Kernel 0a: elementwise tf32 rounding
// ---------------------------------------------------------------------------
__global__ void round_tf32(const float* __restrict__ in, float* __restrict__ out,
                           int n4) {
    int i = blockIdx.x * blockDim.x + threadIdx.x;
    if (i < n4) {
        float4 v = ((const float4*)in)[i];
        v.x = f2tff(v.x); v.y = f2tff(v.y); v.z = f2tff(v.z); v.w = f2tff(v.w);
        ((float4*)out)[i] = v;
    }
}

// ---------------------------------------------------------------------------
// Kernel 0b: transpose + tf32 round. in [R][C] -> out [C][R]
// ---------------------------------------------------------------------------
__global__ void transpose_round(const float* __restrict__ in,
                                float* __restrict__ out, int R, int C) {
    __shared__ float tile[32][33];
    int bx = blockIdx.x * 32;   // C offset
    int by = blockIdx.y * 32;   // R offset
    int x = threadIdx.x, y = threadIdx.y;  // 32 x 8
    #pragma unroll
    for (int j = 0; j < 32; j += 8)
        tile[y + j][x] = in[(size_t)(by + y + j) * C + bx + x];
    __syncthreads();
    #pragma unroll
    for (int j = 0; j < 32; j += 8)
        out[(size_t)(bx + y + j) * R + by + x] = f2tff(tile[x][y + j]);
}

// ---------------------------------------------------------------------------
// Kernel 1: gather relative-position bias into [H, 49, 49]
// ---------------------------------------------------------------------------
__global__ void bias_kernel(const float* __restrict__ table,
                            const int* __restrict__ ridx) {
    int i = blockIdx.x * blockDim.x + threadIdx.x;
    if (i < TOK * TOK * HEADS) {
        int h = i % HEADS;
        int p = i / HEADS;
        g_bias[h * TOK * TOK + p] = table[ridx[p] * HEADS + h];
    }
}

// ---------------------------------------------------------------------------
// Kernel 2/4: tf32 mma.sync GEMM, cp.async 3-stage, ldmatrix fragments.
// C[M,N] = A[M,K] @ BT[N,K]^T + bias[N].  A, BT must be tf32-pre-rounded.
// CTA 128x128, BK=32, 256 thr (8 warps, warp tile 64x32), 1 sync per K-tile.
// K compile-time (384) -> fully unrolled 12-tile pipeline.
// B fragments via ldmatrix.x4 (2 instr per k8-step instead of 4).
// ---------------------------------------------------------------------------
#define GEMM_DYN_BYTES (3 * 32768 + 128)

#define LDSM4(R0, R1, R2, R3, ADDR)                                           \
    asm volatile("ldmatrix.sync.aligned.m8n8.x4.shared.b16 {%0,%1,%2,%3}, [%4];" \
                 : "=r"(R0), "=r"(R1), "=r"(R2), "=r"(R3) : "r"(ADDR))

template <int KC>
__global__ __launch_bounds__(256, 2)
void gemm_tf32(const float* __restrict__ A, const float* __restrict__ BT,
               const float* __restrict__ bias, float* __restrict__ C,
               int M, int N) {
    extern __shared__ char dynraw[];
    unsigned int smem_u = (unsigned int)__cvta_generic_to_shared(dynraw);
    smem_u = (smem_u + 127u) & ~127u;

    int tid  = threadIdx.x;
    int lane = tid & 31;
    int warp = tid >> 5;
    int wm = (warp >> 2) * 64;   // warp m offset (0 or 64)
    int wn = (warp & 3) * 32;    // warp n offset (0,32,64,96)
    int g = lane >> 2;           // 0..7
    int t = lane & 3;            // 0..3

    int bm = blockIdx.y * 128;
    int bn = blockIdx.x * 128;
    const float* Ap = A  + (size_t)bm * KC;
    const float* Bp = BT + (size_t)bn * KC;

    float acc[4][4][4];
    #pragma unroll
    for (int i = 0; i < 4; i++)
        #pragma unroll
        for (int j = 0; j < 4; j++)
            #pragma unroll
            for (int r = 0; r < 4; r++) acc[i][j][r] = 0.f;

    // ldmatrix per-lane addressing
    int mi = lane >> 3;          // matrix index 0..3
    int rr = lane & 7;           // row within 8-row matrix
    // A (x4 per mt): matrices {m=g..g+7 kh0ish} layout proven in R11:
    //   matrix order {k0m0, k0m8, k4m0, k4m8}; lane row = wm+mt*16+(mi&1)*8+rr,
    //   chunk select aCsel = mi>>1.
    unsigned int aRowOff[4];
    #pragma unroll
    for (int mt = 0; mt < 4; mt++)
        aRowOff[mt] = (unsigned int)(wm + mt * 16 + (mi & 1) * 8 + rr) * 128u;
    int aCsel = mi >> 1;
    // B (x4 covering 2 nt x 2 khalf): matrix order {nt0h0, nt0h1, nt1h0, nt1h1}
    //   lane row = wn + ntpair*16 + (mi>>1)*8 + rr, chunk select bKh = mi&1.
    unsigned int bRowOff[2];
    #pragma unroll
    for (int np = 0; np < 2; np++)
        bRowOff[np] = (unsigned int)(wn + np * 16 + (mi >> 1) * 8 + rr) * 128u;
    int bKh = mi & 1;

    #define LOAD_TILE(buf, k0)                                                \
        do {                                                                  \
            unsigned int sA = smem_u + (unsigned int)(buf) * 32768u;          \
            _Pragma("unroll")                                                 \
            for (int i = 0; i < 4; i++) {                                     \
                int ca  = i * 256 + tid;                                      \
                int row = ca >> 3;                                            \
                int ch  = ca & 7;                                             \
                unsigned int d = sA + (unsigned int)row * 128u                \
                                 + (unsigned int)((ch ^ (row & 7)) << 4);     \
                const float* gsa = Ap + (size_t)row * KC + (k0) + ch * 4;     \
                const float* gsb = Bp + (size_t)row * KC + (k0) + ch * 4;     \
                asm volatile("cp.async.cg.shared.global [%0], [%1], 16;"      \
                             :: "r"(d), "l"(gsa));                            \
                asm volatile("cp.async.cg.shared.global [%0], [%1], 16;"      \
                             :: "r"(d + 16384u), "l"(gsb));                   \
            }                                                                 \
            asm volatile("cp.async.commit_group;");                          \
        } while (0)

    #define COMPUTE_TILE(buf)                                                 \
        do {                                                                  \
            unsigned int sA = smem_u + (unsigned int)(buf) * 32768u;          \
            unsigned int sB = sA + 16384u;                                    \
            _Pragma("unroll")                                                 \
            for (int ks = 0; ks < 4; ks++) {                                  \
                int c0 = 2 * ks;                                              \
                unsigned int af[4][4];                                        \
                unsigned int bf[4][2];                                        \
                _Pragma("unroll")                                             \
                for (int mt = 0; mt < 4; mt++) {                              \
                    unsigned int ad = sA + aRowOff[mt]                        \
                        + (unsigned int)((((c0 + aCsel) ^ rr)) << 4);         \
                    LDSM4(af[mt][0], af[mt][1], af[mt][2], af[mt][3], ad);    \
                }                                                             \
                _Pragma("unroll")                                             \
                for (int np = 0; np < 2; np++) {                              \
                    unsigned int bd = sB + bRowOff[np]                        \
                        + (unsigned int)((((c0 + bKh) ^ rr)) << 4);           \
                    LDSM4(bf[np * 2][0], bf[np * 2][1],                       \
                          bf[np * 2 + 1][0], bf[np * 2 + 1][1], bd);          \
                }                                                             \
                _Pragma("unroll")                                             \
                for (int mt = 0; mt < 4; mt++)                                \
                    _Pragma("unroll")                                         \
                    for (int nt = 0; nt < 4; nt++) {                          \
                        asm volatile(                                         \
                            "mma.sync.aligned.m16n8k8.row.col.f32.tf32.tf32.f32 " \
                            "{%0,%1,%2,%3}, {%4,%5,%6,%7}, {%8,%9}, {%0,%1,%2,%3};" \
                            : "+f"(acc[mt][nt][0]), "+f"(acc[mt][nt][1]),     \
                              "+f"(acc[mt][nt][2]), "+f"(acc[mt][nt][3])      \
                            : "r"(af[mt][0]), "r"(af[mt][1]),                 \
                              "r"(af[mt][2]), "r"(af[mt][3]),                 \
                              "r"(bf[nt][0]), "r"(bf[nt][1]));                \
                    }                                                         \
            }                                                                 \
        } while (0)

    constexpr int T = KC / 32;   // 12

    LOAD_TILE(0, 0);
    LOAD_TILE(1, 32);

    #pragma unroll
    for (int tt = 0; tt < T; tt++) {
        if (tt < T - 1) {
            asm volatile("cp.async.wait_group 1;");
        } else {
            asm volatile("cp.async.wait_group 0;");
        }
        __syncthreads();
        if (tt + 2 < T) {
            LOAD_TILE((tt + 2) % 3, (tt + 2) * 32);
        }
        COMPUTE_TILE(tt % 3);
    }
    #undef LOAD_TILE
    #undef COMPUTE_TILE

    // epilogue: c0:(g,2t) c1:(g,2t+1) c2:(g+8,2t) c3:(g+8,2t+1)
    #pragma unroll
    for (int mt = 0; mt < 4; mt++) {
        int row0 = bm + wm + mt * 16 + g;
        #pragma unroll
        for (int nt = 0; nt < 4; nt++) {
            int col = bn + wn + nt * 8 + 2 * t;
            float bx = bias[col], by = bias[col + 1];
            float2 o0 = make_float2(acc[mt][nt][0] + bx, acc[mt][nt][1] + by);
            float2 o1 = make_float2(acc[mt][nt][2] + bx, acc[mt][nt][3] + by);
            *(float2*)&C[(size_t)row0 * N + col]       = o0;
            *(float2*)&C[(size_t)(row0 + 8) * N + col] = o1;
        }
    }
}

// ---------------------------------------------------------------------------
// Kernel 3: windowed attention (R9 proven), output rounded to tf32.
// ---------------------------------------------------------------------------
#define TOKP 52
#define ATHR 192
__global__ __launch_bounds__(ATHR)
void attn_kernel(float* __restrict__ out) {
    int w = blockIdx.x;
    int h = blockIdx.y;
    __shared__ float qT[HD][TOKP];
    __shared__ float kT[HD][TOKP];
    __shared__ float v[TOK][HD];
    __shared__ float sT[TOKP][TOKP];   // sT[j][i] = S[i][j]

    int tid = threadIdx.x;
    const float scale = 0.17677669529663687f;  // 32^-0.5

    for (int i = tid; i < HD * 3; i += ATHR) {
        int dd = i / 3, tp = TOK + i % 3;
        qT[dd][tp] = 0.f;
        kT[dd][tp] = 0.f;
    }

    size_t base = (size_t)w * TOK * QKV_N + (size_t)h * HD;
    for (int i = tid; i < TOK * (HD / 4); i += ATHR) {
        int t = i / (HD / 4), dq = (i % (HD / 4)) * 4;
        const float* row = g_qkv + base + (size_t)t * QKV_N + dq;
        float4 qv = *(const float4*)(row);
        float4 kv = *(const float4*)(row + DIM);
        float4 vv = *(const float4*)(row + 2 * DIM);
        qT[dq + 0][t] = qv.x * scale;
        qT[dq + 1][t] = qv.y * scale;
        qT[dq + 2][t] = qv.z * scale;
        qT[dq + 3][t] = qv.w * scale;
        kT[dq + 0][t] = kv.x;
        kT[dq + 1][t] = kv.y;
        kT[dq + 2][t] = kv.z;
        kT[dq + 3][t] = kv.w;
        *(float4*)&v[t][dq] = vv;
    }
    __syncthreads();

    const float* bptr = g_bias + h * TOK * TOK;
    if (tid < 169) {
        int i0 = (tid / 13) * 4;
        int j0 = (tid % 13) * 4;
        float acc[4][4];
        #pragma unroll
        for (int r = 0; r < 4; r++)
            #pragma unroll
            for (int c = 0; c < 4; c++) acc[r][c] = 0.f;
        #pragma unroll
        for (int dd = 0; dd < HD; dd++) {
            float4 qa = *(const float4*)&qT[dd][i0];
            float4 ka = *(const float4*)&kT[dd][j0];
            float qr[4] = {qa.x, qa.y, qa.z, qa.w};
            float kc[4] = {ka.x, ka.y, ka.z, ka.w};
            #pragma unroll
            for (int r = 0; r < 4; r++)
                #pragma unroll
                for (int c = 0; c < 4; c++)
                    acc[r][c] = fmaf(qr[r], kc[c], acc[r][c]);
        }
        #pragma unroll
        for (int c = 0; c < 4; c++) {
            int j = j0 + c;
            float4 o;
            float b0 = (i0 + 0 < TOK && j < TOK) ? bptr[(i0 + 0) * TOK + j] : 0.f;
            float b1 = (i0 + 1 < TOK && j < TOK) ? bptr[(i0 + 1) * TOK + j] : 0.f;
            float b2 = (i0 + 2 < TOK && j < TOK) ? bptr[(i0 + 2) * TOK + j] : 0.f;
            float b3 = (i0 + 3 < TOK && j < TOK) ? bptr[(i0 + 3) * TOK + j] : 0.f;
            o.x = acc[0][c] + b0;
            o.y = acc[1][c] + b1;
            o.z = acc[2][c] + b2;
            o.w = acc[3][c] + b3;
            *(float4*)&sT[j][i0] = o;
        }
    }
    __syncthreads();

    if (tid < TOK) {
        float mx = -1e30f;
        #pragma unroll 7
        for (int j = 0; j < TOK; j++) mx = fmaxf(mx, sT[j][tid]);
        float sum = 0.f;
        #pragma unroll 7
        for (int j = 0; j < TOK; j++) {
            float e = __expf(sT[j][tid] - mx);
            sT[j][tid] = e;
            sum += e;
        }
        float inv = 1.0f / sum;
        #pragma unroll 7
        for (int j = 0; j < TOK; j++) sT[j][tid] *= inv;
    }
    __syncthreads();

    if (tid < 104) {
        int i0 = (tid >> 3) * 4;
        int dq = (tid & 7) * 4;
        float acc[4][4];
        #pragma unroll
        for (int r = 0; r < 4; r++)
            #pragma unroll
            for (int c = 0; c < 4; c++) acc[r][c] = 0.f;
        #pragma unroll 7
        for (int j = 0; j < TOK; j++) {
            float4 sa = *(const float4*)&sT[j][i0];
            float4 va = *(const float4*)&v[j][dq];
            float sr[4] = {sa.x, sa.y, sa.z, sa.w};
            float vc[4] = {va.x, va.y, va.z, va.w};
            #pragma unroll
            for (int r = 0; r < 4; r++)
                #pragma unroll
                for (int c = 0; c < 4; c++)
                    acc[r][c] = fmaf(sr[r], vc[c], acc[r][c]);
        }
        #pragma unroll
        for (int r = 0; r < 4; r++) {
            int i = i0 + r;
            if (i < TOK) {
                float4 o = make_float4(f2tff(acc[r][0]), f2tff(acc[r][1]),
                                       f2tff(acc[r][2]), f2tff(acc[r][3]));
                *(float4*)&out[((size_t)w * TOK + i) * DIM + h * HD + dq] = o;
            }
        }
    }
}

// ---------------------------------------------------------------------------
extern "C" void kernel_launch(void* const* d_in, const int* in_sizes, int n_in,
                              void* d_out, int out_size) {
    const float* x       = (const float*)d_in[0];
    const float* qkv_w   = (const float*)d_in[1];
    const float* qkv_b   = (const float*)d_in[2];
    const float* proj_w  = (const float*)d_in[3];
    const float* proj_b  = (const float*)d_in[4];
    const float* table   = (const float*)d_in[5];
    const int*   ridx    = (const int*)d_in[6];
    float*       out     = (float*)d_out;

    float *xr = nullptr, *w1t = nullptr, *w2t = nullptr;
    float *qkv_buf = nullptr, *att_buf = nullptr;
    cudaGetSymbolAddress((void**)&xr, g_x);
    cudaGetSymbolAddress((void**)&w1t, g_w1t);
    cudaGetSymbolAddress((void**)&w2t, g_w2t);
    cudaGetSymbolAddress((void**)&qkv_buf, g_qkv);
    cudaGetSymbolAddress((void**)&att_buf, g_att);

    cudaFuncSetAttribute(gemm_tf32<DIM>,
                         cudaFuncAttributeMaxDynamicSharedMemorySize,
                         GEMM_DYN_BYTES);

    // 0. round x; transpose+round weights; bias gather
    {
        int n4 = (M_TOTAL * DIM) / 4;
        round_tf32<<<(n4 + 255) / 256, 256>>>(x, xr, n4);
        dim3 blk(32, 8);
        transpose_round<<<dim3(QKV_N / 32, DIM / 32), blk>>>(qkv_w, w1t, DIM, QKV_N);
        transpose_round<<<dim3(DIM / 32, DIM / 32), blk>>>(proj_w, w2t, DIM, DIM);
        int total = TOK * TOK * HEADS;
        bias_kernel<<<(total + 255) / 256, 256>>>(table, ridx);
    }
    // 2. QKV GEMM: [100352,384] @ [384,1152] + qkv_b
    {
        dim3 grid(QKV_N / 128, M_TOTAL / 128);   // (9, 784)
        gemm_tf32<DIM><<<grid, 256, GEMM_DYN_BYTES>>>(xr, w1t, qkv_b, qkv_buf,
                                                      M_TOTAL, QKV_N);
    }
    // 3. window attention
    {
        dim3 grid(NWIN, HEADS);                  // (2048, 12)
        attn_kernel<<<grid, ATHR>>>(att_buf);
    }
    // 4. proj GEMM: [100352,384] @ [384,384] + proj_b -> d_out
    {
        dim3 grid(DIM / 128, M_TOTAL / 128);     // (3, 784)
        gemm_tf32<DIM><<<grid, 256, GEMM_DYN_BYTES>>>(att_buf, w2t, proj_b, out,
                                                      M_TOTAL, DIM);
    }
}